// round 1
// baseline (speedup 1.0000x reference)
#include <cuda_runtime.h>
#include <math.h>
#include <cfloat>

#define B_   128
#define N_   8732
#define C_   512
#define H_   19
#define FG_  19
#define HID_ 4096

// scratch (device globals — no allocation allowed)
__device__ float g_feat[B_*C_];
__device__ float g_h1[B_*HID_];
__device__ float g_h2[B_*HID_];
__device__ int   g_bins[B_*4];
__device__ int   g_valid[B_];

// ---------------------------------------------------------------------------
// Kernel 1: per-batch best car prior -> decode -> clip -> boxes/valid + bins
// ---------------------------------------------------------------------------
__global__ void best_prior_kernel(const float* __restrict__ loc,
                                  const float* __restrict__ conf,
                                  const float* __restrict__ priors,
                                  float* __restrict__ out)
{
    int b = blockIdx.x, tid = threadIdx.x;
    const float* cb = conf + (size_t)b * N_ * 2;

    float best = -FLT_MAX;
    int   bidx = 0x7fffffff;
    int   anyc = 0;

    for (int i = tid; i < N_; i += 256) {
        float c0 = cb[2*i], c1 = cb[2*i+1];
        if (c1 > c0) {                       // argmax(softmax)==1 iff c1>c0 (strict)
            anyc = 1;
            float p1 = 1.0f / (1.0f + expf(c0 - c1));   // softmax prob of class 1
            if (p1 > best || (p1 == best && i < bidx)) { best = p1; bidx = i; }
        }
    }

    int has = __syncthreads_or(anyc);

    __shared__ float sv[256];
    __shared__ int   si[256];
    sv[tid] = best; si[tid] = bidx;
    __syncthreads();
    for (int s = 128; s > 0; s >>= 1) {
        if (tid < s) {
            float v2 = sv[tid+s]; int i2 = si[tid+s];
            if (v2 > sv[tid] || (v2 == sv[tid] && i2 < si[tid])) { sv[tid]=v2; si[tid]=i2; }
        }
        __syncthreads();
    }

    if (tid == 0) {
        float bx0=0.f,bx1=0.f,bx2=0.f,bx3=0.f;
        int v = 0;
        int n0=0,n1=0,n2=0,n3=0;
        if (has) {
            int idx = si[0];
            float p0 = priors[4*idx+0], p1p = priors[4*idx+1];
            float p2 = priors[4*idx+2], p3  = priors[4*idx+3];
            const float* l = loc + ((size_t)b * N_ + idx) * 4;
            float cx = p0 + l[0] * 0.1f * p2;
            float cy = p1p + l[1] * 0.1f * p3;
            float w  = p2 * expf(l[2] * 0.2f);
            float h  = p3 * expf(l[3] * 0.2f);
            float x1 = cx - 0.5f*w, y1 = cy - 0.5f*h;
            float x2 = x1 + w,      y2 = y1 + h;
            v = (x2 > x1) && (y2 > y1);
            bx0 = fminf(fmaxf(x1, 0.f), 1.f);
            bx1 = fminf(fmaxf(y1, 0.f), 1.f);
            bx2 = fminf(fmaxf(x2, 0.f), 1.f);
            bx3 = fminf(fmaxf(y2, 0.f), 1.f);
            const float step = (float)(300.0 / 19.0);
            float t;
            t = fminf(fmaxf(bx0*300.0f,0.f),300.f)/step; n0 = (int)floorf(fminf(fmaxf(t,0.f),18.f));
            t = fminf(fmaxf(bx1*300.0f,0.f),300.f)/step; n1 = (int)floorf(fminf(fmaxf(t,0.f),18.f));
            t = fminf(fmaxf(bx2*300.0f,0.f),300.f)/step; n2 = (int)floorf(fminf(fmaxf(t,0.f),18.f));
            t = fminf(fmaxf(bx3*300.0f,0.f),300.f)/step; n3 = (int)floorf(fminf(fmaxf(t,0.f),18.f));
        }
        // boxes at [2432, 2944), valid at [2944, 3072)
        out[2432 + b*4 + 0] = bx0;
        out[2432 + b*4 + 1] = bx1;
        out[2432 + b*4 + 2] = bx2;
        out[2432 + b*4 + 3] = bx3;
        out[2944 + b] = v ? 1.0f : 0.0f;
        g_valid[b]   = v;
        g_bins[b*4+0] = n0; g_bins[b*4+1] = n1;
        g_bins[b*4+2] = n2; g_bins[b*4+3] = n3;
    }
}

// ---------------------------------------------------------------------------
// Kernel 2: masked global max pool over box region -> g_feat [B, C]
// one warp per (batch, channel)
// ---------------------------------------------------------------------------
__global__ void extract_kernel(const float* __restrict__ feats)
{
    int b    = blockIdx.x;
    int warp = threadIdx.x >> 5;
    int lane = threadIdx.x & 31;
    int c    = blockIdx.y * 8 + warp;

    if (!g_valid[b]) { if (lane == 0) g_feat[b*C_ + c] = 0.f; return; }

    int x1 = g_bins[b*4+0], y1 = g_bins[b*4+1];
    int x2 = g_bins[b*4+2], y2 = g_bins[b*4+3];
    int W = x2 - x1 + 1;
    int T = (y2 - y1 + 1) * W;

    const float* f = feats + ((size_t)(b * C_ + c)) * (H_ * H_);
    float m = -FLT_MAX;
    for (int t = lane; t < T; t += 32) {
        int y = y1 + t / W, x = x1 + t % W;
        m = fmaxf(m, f[y * H_ + x]);
    }
    #pragma unroll
    for (int o = 16; o; o >>= 1) m = fmaxf(m, __shfl_xor_sync(0xffffffffu, m, o));
    if (lane == 0) g_feat[b*C_ + c] = m;
}

// ---------------------------------------------------------------------------
// Kernel 3: tiled SGEMM  C[M,N] = relu?(A[M,K] @ B[K,N] + bias)
// BM=BN=64, BK=16, 256 threads, 4x4 per thread
// ---------------------------------------------------------------------------
template<bool RELU>
__global__ void gemm_k(int N, int K,
                       const float* __restrict__ A, const float* __restrict__ Bw,
                       const float* __restrict__ bias, float* __restrict__ C)
{
    __shared__ __align__(16) float As[16][68];
    __shared__ __align__(16) float Bs[16][68];

    int tid = threadIdx.x;
    int n0 = blockIdx.x * 64, m0 = blockIdx.y * 64;
    int tx = tid & 15, ty = tid >> 4;

    float acc[4][4] = {};

    for (int k0 = 0; k0 < K; k0 += 16) {
        #pragma unroll
        for (int j = 0; j < 4; j++) {
            int idx = tid + j * 256;
            As[idx & 15][idx >> 4] = A[(size_t)(m0 + (idx >> 4)) * K + k0 + (idx & 15)];
            Bs[idx >> 6][idx & 63] = Bw[(size_t)(k0 + (idx >> 6)) * N + n0 + (idx & 63)];
        }
        __syncthreads();
        #pragma unroll
        for (int kk = 0; kk < 16; kk++) {
            float4 a4 = *(const float4*)&As[kk][ty * 4];
            float4 b4 = *(const float4*)&Bs[kk][tx * 4];
            float a[4] = {a4.x, a4.y, a4.z, a4.w};
            float bb[4] = {b4.x, b4.y, b4.z, b4.w};
            #pragma unroll
            for (int i = 0; i < 4; i++)
                #pragma unroll
                for (int j = 0; j < 4; j++)
                    acc[i][j] += a[i] * bb[j];
        }
        __syncthreads();
    }

    #pragma unroll
    for (int i = 0; i < 4; i++) {
        int m = m0 + ty * 4 + i;
        #pragma unroll
        for (int j = 0; j < 4; j++) {
            int n = n0 + tx * 4 + j;
            float v = acc[i][j] + bias[n];
            if (RELU) v = fmaxf(v, 0.f);
            C[(size_t)m * N + n] = v;
        }
    }
}

// ---------------------------------------------------------------------------
// Kernel 4: final FC  out[B,19] = h2 @ w3 + b3   (K=4096, N=19)
// one block per batch row; smem-cached row; one warp per column group
// ---------------------------------------------------------------------------
__global__ void fc3_kernel(const float* __restrict__ A, const float* __restrict__ W,
                           const float* __restrict__ bias, float* __restrict__ out)
{
    int b = blockIdx.x;
    int tid = threadIdx.x, warp = tid >> 5, lane = tid & 31;
    __shared__ float sh[HID_];
    const float* a = A + (size_t)b * HID_;
    for (int i = tid; i < HID_; i += 256) sh[i] = a[i];
    __syncthreads();
    for (int col = warp; col < FG_; col += 8) {
        float s = 0.f;
        for (int k = lane; k < HID_; k += 32) s += sh[k] * W[(size_t)k * FG_ + col];
        #pragma unroll
        for (int o = 16; o; o >>= 1) s += __shfl_xor_sync(0xffffffffu, s, o);
        if (lane == 0) out[b * FG_ + col] = s + bias[col];
    }
}

// ---------------------------------------------------------------------------
extern "C" void kernel_launch(void* const* d_in, const int* in_sizes, int n_in,
                              void* d_out, int out_size)
{
    const float* loc      = (const float*)d_in[0];
    const float* conf     = (const float*)d_in[1];
    const float* priors   = (const float*)d_in[2];
    const float* features = (const float*)d_in[3];
    const float* w1 = (const float*)d_in[4];
    const float* b1 = (const float*)d_in[5];
    const float* w2 = (const float*)d_in[6];
    const float* b2 = (const float*)d_in[7];
    const float* w3 = (const float*)d_in[8];
    const float* b3 = (const float*)d_in[9];
    float* out = (float*)d_out;

    void *pf, *p1, *p2;
    cudaGetSymbolAddress(&pf, g_feat);
    cudaGetSymbolAddress(&p1, g_h1);
    cudaGetSymbolAddress(&p2, g_h2);

    best_prior_kernel<<<B_, 256>>>(loc, conf, priors, out);
    extract_kernel<<<dim3(B_, C_/8), 256>>>(features);
    gemm_k<true><<<dim3(HID_/64, B_/64), 256>>>(HID_, C_,   (const float*)pf, w1, b1, (float*)p1);
    gemm_k<true><<<dim3(HID_/64, B_/64), 256>>>(HID_, HID_, (const float*)p1, w2, b2, (float*)p2);
    fc3_kernel<<<B_, 256>>>((const float*)p2, w3, b3, out);
}

// round 3
// speedup vs baseline: 2.1748x; 2.1748x over previous
#include <cuda_runtime.h>
#include <math.h>
#include <cfloat>
#include <cstdint>

#define B_   128
#define N_   8732
#define C_   512
#define H_   19
#define FG_  19
#define HID_ 4096

// ---------------------------------------------------------------------------
// scratch (device globals — no allocation allowed)
// ---------------------------------------------------------------------------
__device__ float g_feat[B_*C_];
__device__ float g_h1[B_*HID_];
__device__ float g_h2[B_*HID_];
__device__ int   g_bins[B_*4];
__device__ int   g_valid[B_];
__device__ float g_part[8*B_*HID_];     // 16 MB split-K partials

__device__ __forceinline__ float tf32_rd(float x) {
    uint32_t u;
    asm("cvt.rna.tf32.f32 %0, %1;" : "=r"(u) : "f"(x));
    return __uint_as_float(u);
}

#define MMA_TF32(c, a, b0, b1)                                              \
    asm volatile("mma.sync.aligned.m16n8k8.row.col.f32.tf32.tf32.f32 "      \
        "{%0,%1,%2,%3}, {%4,%5,%6,%7}, {%8,%9}, {%0,%1,%2,%3};"             \
        : "+f"((c)[0]), "+f"((c)[1]), "+f"((c)[2]), "+f"((c)[3])            \
        : "r"((a)[0]), "r"((a)[1]), "r"((a)[2]), "r"((a)[3]),               \
          "r"(b0), "r"(b1))

// ---------------------------------------------------------------------------
// Kernel 1: per-batch best car prior -> decode -> clip -> boxes/valid + bins
// ---------------------------------------------------------------------------
__global__ void best_prior_kernel(const float* __restrict__ loc,
                                  const float* __restrict__ conf,
                                  const float* __restrict__ priors,
                                  float* __restrict__ out)
{
    int b = blockIdx.x, tid = threadIdx.x;
    const float* cb = conf + (size_t)b * N_ * 2;

    float best = -FLT_MAX;
    int   bidx = 0x7fffffff;
    int   anyc = 0;

    for (int i = tid; i < N_; i += 256) {
        float c0 = cb[2*i], c1 = cb[2*i+1];
        if (c1 > c0) {
            anyc = 1;
            float p1 = 1.0f / (1.0f + expf(c0 - c1));
            if (p1 > best || (p1 == best && i < bidx)) { best = p1; bidx = i; }
        }
    }

    int has = __syncthreads_or(anyc);

    __shared__ float sv[256];
    __shared__ int   si[256];
    sv[tid] = best; si[tid] = bidx;
    __syncthreads();
    for (int s = 128; s > 0; s >>= 1) {
        if (tid < s) {
            float v2 = sv[tid+s]; int i2 = si[tid+s];
            if (v2 > sv[tid] || (v2 == sv[tid] && i2 < si[tid])) { sv[tid]=v2; si[tid]=i2; }
        }
        __syncthreads();
    }

    if (tid == 0) {
        float bx0=0.f,bx1=0.f,bx2=0.f,bx3=0.f;
        int v = 0;
        int n0=0,n1=0,n2=0,n3=0;
        if (has) {
            int idx = si[0];
            float p0 = priors[4*idx+0], p1p = priors[4*idx+1];
            float p2 = priors[4*idx+2], p3  = priors[4*idx+3];
            const float* l = loc + ((size_t)b * N_ + idx) * 4;
            float cx = p0 + l[0] * 0.1f * p2;
            float cy = p1p + l[1] * 0.1f * p3;
            float w  = p2 * expf(l[2] * 0.2f);
            float h  = p3 * expf(l[3] * 0.2f);
            float x1 = cx - 0.5f*w, y1 = cy - 0.5f*h;
            float x2 = x1 + w,      y2 = y1 + h;
            v = (x2 > x1) && (y2 > y1);
            bx0 = fminf(fmaxf(x1, 0.f), 1.f);
            bx1 = fminf(fmaxf(y1, 0.f), 1.f);
            bx2 = fminf(fmaxf(x2, 0.f), 1.f);
            bx3 = fminf(fmaxf(y2, 0.f), 1.f);
            const float step = (float)(300.0 / 19.0);
            float t;
            t = fminf(fmaxf(bx0*300.0f,0.f),300.f)/step; n0 = (int)floorf(fminf(fmaxf(t,0.f),18.f));
            t = fminf(fmaxf(bx1*300.0f,0.f),300.f)/step; n1 = (int)floorf(fminf(fmaxf(t,0.f),18.f));
            t = fminf(fmaxf(bx2*300.0f,0.f),300.f)/step; n2 = (int)floorf(fminf(fmaxf(t,0.f),18.f));
            t = fminf(fmaxf(bx3*300.0f,0.f),300.f)/step; n3 = (int)floorf(fminf(fmaxf(t,0.f),18.f));
        }
        out[2432 + b*4 + 0] = bx0;
        out[2432 + b*4 + 1] = bx1;
        out[2432 + b*4 + 2] = bx2;
        out[2432 + b*4 + 3] = bx3;
        out[2944 + b] = v ? 1.0f : 0.0f;
        g_valid[b]   = v;
        g_bins[b*4+0] = n0; g_bins[b*4+1] = n1;
        g_bins[b*4+2] = n2; g_bins[b*4+3] = n3;
    }
}

// ---------------------------------------------------------------------------
// Kernel 2: masked global max pool over box region -> g_feat [B, C]
// ---------------------------------------------------------------------------
__global__ void extract_kernel(const float* __restrict__ feats)
{
    int b    = blockIdx.x;
    int warp = threadIdx.x >> 5;
    int lane = threadIdx.x & 31;
    int c    = blockIdx.y * 8 + warp;

    if (!g_valid[b]) { if (lane == 0) g_feat[b*C_ + c] = 0.f; return; }

    int x1 = g_bins[b*4+0], y1 = g_bins[b*4+1];
    int x2 = g_bins[b*4+2], y2 = g_bins[b*4+3];
    int W = x2 - x1 + 1;
    int T = (y2 - y1 + 1) * W;

    const float* f = feats + ((size_t)(b * C_ + c)) * (H_ * H_);
    float m = -FLT_MAX;
    for (int t = lane; t < T; t += 32) {
        int y = y1 + t / W, x = x1 + t % W;
        m = fmaxf(m, f[y * H_ + x]);
    }
    #pragma unroll
    for (int o = 16; o; o >>= 1) m = fmaxf(m, __shfl_xor_sync(0xffffffffu, m, o));
    if (lane == 0) g_feat[b*C_ + c] = m;
}

// ---------------------------------------------------------------------------
// Kernel 3: 3xTF32 mma.sync GEMM, split-K.
//   part[split][128][HID_] = A[128, Ktot] @ Bw[Ktot, HID_]  (partial K sums)
//   A K-contiguous [128, Ktot]; Bw N-contiguous [Ktot, HID_] (native layout).
//   Block: BM=128, BN=128, BK=32; 8 warps, each 64x32 (4 m16 x 4 n8 tiles).
// ---------------------------------------------------------------------------
__global__ __launch_bounds__(256)
void gemm_mma_kernel(int Ktot, int KSPLIT,
                     const float* __restrict__ A, const float* __restrict__ Bw,
                     float* __restrict__ part)
{
    __shared__ float As[128][36];   // [row][k], pad 36 (144B rows, 16-aligned)
    __shared__ float Bs[32][132];   // [k][n],  pad 132 (528B rows, 16-aligned)

    const int tid  = threadIdx.x;
    const int wid  = tid >> 5;
    const int lane = tid & 31;
    const int gid  = lane >> 2;     // group id 0..7
    const int tig  = lane & 3;      // thread in group 0..3
    const int n0   = blockIdx.x * 128;
    const int ks   = blockIdx.y * KSPLIT;
    const int NCH  = KSPLIT >> 5;
    const int mbase = (wid & 1) * 64;
    const int nbase = (wid >> 1) * 32;

    float acc[16][4];
    #pragma unroll
    for (int i = 0; i < 16; i++)
        #pragma unroll
        for (int j = 0; j < 4; j++) acc[i][j] = 0.f;

    // prefetch chunk 0 into registers
    float4 ra[4], rb[4];
    {
        #pragma unroll
        for (int j = 0; j < 4; j++) {
            int f4 = tid + j * 256;
            int arow = f4 >> 3, aq = f4 & 7;
            ra[j] = *(const float4*)(A + (size_t)arow * Ktot + ks + aq * 4);
            int brow = f4 >> 5, bc = f4 & 31;
            rb[j] = *(const float4*)(Bw + (size_t)(ks + brow) * HID_ + n0 + bc * 4);
        }
    }

    for (int c = 0; c < NCH; c++) {
        // store staged registers into SMEM
        #pragma unroll
        for (int j = 0; j < 4; j++) {
            int f4 = tid + j * 256;
            int arow = f4 >> 3, aq = f4 & 7;
            *(float4*)&As[arow][aq * 4] = ra[j];
            int brow = f4 >> 5, bc = f4 & 31;
            *(float4*)&Bs[brow][bc * 4] = rb[j];
        }
        __syncthreads();

        // prefetch next chunk
        if (c + 1 < NCH) {
            int k0 = ks + (c + 1) * 32;
            #pragma unroll
            for (int j = 0; j < 4; j++) {
                int f4 = tid + j * 256;
                int arow = f4 >> 3, aq = f4 & 7;
                ra[j] = *(const float4*)(A + (size_t)arow * Ktot + k0 + aq * 4);
                int brow = f4 >> 5, bc = f4 & 31;
                rb[j] = *(const float4*)(Bw + (size_t)(k0 + brow) * HID_ + n0 + bc * 4);
            }
        }

        // compute: 4 k8 steps over BK=32
        #pragma unroll
        for (int kk = 0; kk < 4; kk++) {
            const int kb = kk * 8;

            // A fragments for the 4 m16 tiles, split hi/lo
            uint32_t ahi[4][4], alo[4][4];
            #pragma unroll
            for (int mt = 0; mt < 4; mt++) {
                int r = mbase + mt * 16 + gid;
                float x0 = As[r][kb + tig];
                float x1 = As[r + 8][kb + tig];
                float x2 = As[r][kb + tig + 4];
                float x3 = As[r + 8][kb + tig + 4];
                float h0 = tf32_rd(x0), h1 = tf32_rd(x1),
                      h2 = tf32_rd(x2), h3 = tf32_rd(x3);
                ahi[mt][0] = __float_as_uint(h0); alo[mt][0] = __float_as_uint(tf32_rd(x0 - h0));
                ahi[mt][1] = __float_as_uint(h1); alo[mt][1] = __float_as_uint(tf32_rd(x1 - h1));
                ahi[mt][2] = __float_as_uint(h2); alo[mt][2] = __float_as_uint(tf32_rd(x2 - h2));
                ahi[mt][3] = __float_as_uint(h3); alo[mt][3] = __float_as_uint(tf32_rd(x3 - h3));
            }

            #pragma unroll
            for (int nt = 0; nt < 4; nt++) {
                int col = nbase + nt * 8 + gid;
                float y0 = Bs[kb + tig][col];
                float y1 = Bs[kb + tig + 4][col];
                float g0 = tf32_rd(y0), g1 = tf32_rd(y1);
                uint32_t bhi0 = __float_as_uint(g0);
                uint32_t bhi1 = __float_as_uint(g1);
                uint32_t blo0 = __float_as_uint(tf32_rd(y0 - g0));
                uint32_t blo1 = __float_as_uint(tf32_rd(y1 - g1));

                #pragma unroll
                for (int mt = 0; mt < 4; mt++) {
                    MMA_TF32(acc[mt * 4 + nt], ahi[mt], bhi0, bhi1);
                    MMA_TF32(acc[mt * 4 + nt], ahi[mt], blo0, blo1);
                    MMA_TF32(acc[mt * 4 + nt], alo[mt], bhi0, bhi1);
                }
            }
        }
        __syncthreads();
    }

    // epilogue: write partial sums
    #pragma unroll
    for (int mt = 0; mt < 4; mt++) {
        int row = mbase + mt * 16 + gid;
        float* base0 = part + ((size_t)blockIdx.y * 128 + row) * HID_ + n0;
        float* base1 = base0 + (size_t)8 * HID_;
        #pragma unroll
        for (int nt = 0; nt < 4; nt++) {
            int col = nbase + nt * 8 + tig * 2;
            float2 v0 = make_float2(acc[mt*4+nt][0], acc[mt*4+nt][1]);
            float2 v1 = make_float2(acc[mt*4+nt][2], acc[mt*4+nt][3]);
            *(float2*)(base0 + col) = v0;
            *(float2*)(base1 + col) = v1;
        }
    }
}

// ---------------------------------------------------------------------------
// Kernel 4: split-K reduce + bias + relu
// ---------------------------------------------------------------------------
template<bool RELU>
__global__ void reduce_bias_kernel(int S, const float* __restrict__ part,
                                   const float* __restrict__ bias,
                                   float* __restrict__ out)
{
    int i4 = blockIdx.x * 256 + threadIdx.x;
    const int MN = B_ * HID_;
    int base = i4 * 4;
    if (base >= MN) return;
    float4 s = make_float4(0.f, 0.f, 0.f, 0.f);
    for (int p = 0; p < S; p++) {
        float4 v = *(const float4*)(part + (size_t)p * MN + base);
        s.x += v.x; s.y += v.y; s.z += v.z; s.w += v.w;
    }
    int n = base & (HID_ - 1);
    s.x += bias[n + 0]; s.y += bias[n + 1]; s.z += bias[n + 2]; s.w += bias[n + 3];
    if (RELU) {
        s.x = fmaxf(s.x, 0.f); s.y = fmaxf(s.y, 0.f);
        s.z = fmaxf(s.z, 0.f); s.w = fmaxf(s.w, 0.f);
    }
    *(float4*)(out + base) = s;
}

// ---------------------------------------------------------------------------
// Kernel 5: final FC  out[B,19] = h2 @ w3 + b3
// ---------------------------------------------------------------------------
__global__ void fc3_kernel(const float* __restrict__ A, const float* __restrict__ W,
                           const float* __restrict__ bias, float* __restrict__ out)
{
    int b = blockIdx.x;
    int tid = threadIdx.x, warp = tid >> 5, lane = tid & 31;
    __shared__ float sh[HID_];
    const float* a = A + (size_t)b * HID_;
    for (int i = tid; i < HID_; i += 256) sh[i] = a[i];
    __syncthreads();
    for (int col = warp; col < FG_; col += 8) {
        float s = 0.f;
        for (int k = lane; k < HID_; k += 32) s += sh[k] * W[(size_t)k * FG_ + col];
        #pragma unroll
        for (int o = 16; o; o >>= 1) s += __shfl_xor_sync(0xffffffffu, s, o);
        if (lane == 0) out[b * FG_ + col] = s + bias[col];
    }
}

// ---------------------------------------------------------------------------
extern "C" void kernel_launch(void* const* d_in, const int* in_sizes, int n_in,
                              void* d_out, int out_size)
{
    const float* loc      = (const float*)d_in[0];
    const float* conf     = (const float*)d_in[1];
    const float* priors   = (const float*)d_in[2];
    const float* features = (const float*)d_in[3];
    const float* w1 = (const float*)d_in[4];
    const float* b1 = (const float*)d_in[5];
    const float* w2 = (const float*)d_in[6];
    const float* b2 = (const float*)d_in[7];
    const float* w3 = (const float*)d_in[8];
    const float* b3 = (const float*)d_in[9];
    float* out = (float*)d_out;

    void *pf, *p1, *p2, *ppart;
    cudaGetSymbolAddress(&pf,    g_feat);
    cudaGetSymbolAddress(&p1,    g_h1);
    cudaGetSymbolAddress(&p2,    g_h2);
    cudaGetSymbolAddress(&ppart, g_part);

    best_prior_kernel<<<B_, 256>>>(loc, conf, priors, out);
    extract_kernel<<<dim3(B_, C_/8), 256>>>(features);

    // GEMM1: [128,512] @ [512,4096], split-K=4 (128 K each)
    gemm_mma_kernel<<<dim3(HID_/128, 4), 256>>>(C_, 128,
        (const float*)pf, w1, (float*)ppart);
    reduce_bias_kernel<true><<<(B_*HID_/4 + 255)/256, 256>>>(4,
        (const float*)ppart, b1, (float*)p1);

    // GEMM2: [128,4096] @ [4096,4096], split-K=8 (512 K each)
    gemm_mma_kernel<<<dim3(HID_/128, 8), 256>>>(HID_, 512,
        (const float*)p1, w2, (float*)ppart);
    reduce_bias_kernel<true><<<(B_*HID_/4 + 255)/256, 256>>>(8,
        (const float*)ppart, b2, (float*)p2);

    fc3_kernel<<<B_, 256>>>((const float*)p2, w3, b3, out);
}

// round 5
// speedup vs baseline: 2.3025x; 1.0587x over previous
#include <cuda_runtime.h>
#include <cuda_bf16.h>
#include <math.h>
#include <cfloat>
#include <cstdint>

#define B_   128
#define N_   8732
#define C_   512
#define H_   19
#define FG_  19
#define HID_ 4096

// ---------------------------------------------------------------------------
// scratch (device globals — no allocation allowed)
// ---------------------------------------------------------------------------
__device__ float g_feat[B_*C_];
__device__ float g_h1[B_*HID_];
__device__ float g_h2[B_*HID_];
__device__ int   g_bins[B_*4];
__device__ int   g_valid[B_];
__device__ float g_part[4*B_*HID_];     // split-K partials (S<=4)

// ---------------------------------------------------------------------------
// helpers
// ---------------------------------------------------------------------------
#define MMA_BF16(c, a, b0, b1)                                              \
    asm volatile("mma.sync.aligned.m16n8k16.row.col.f32.bf16.bf16.f32 "     \
        "{%0,%1,%2,%3}, {%4,%5,%6,%7}, {%8,%9}, {%0,%1,%2,%3};"             \
        : "+f"((c)[0]), "+f"((c)[1]), "+f"((c)[2]), "+f"((c)[3])            \
        : "r"((a)[0]), "r"((a)[1]), "r"((a)[2]), "r"((a)[3]),               \
          "r"(b0), "r"(b1))

// split x0,x1 into bf16 hi/lo planes, packed as bf16x2 (x0 in low half)
__device__ __forceinline__ void split_pack(float x0, float x1,
                                           uint32_t& hi, uint32_t& lo)
{
    __nv_bfloat16 h0 = __float2bfloat16_rn(x0);
    __nv_bfloat16 h1 = __float2bfloat16_rn(x1);
    float r0 = x0 - __bfloat162float(h0);
    float r1 = x1 - __bfloat162float(h1);
    __nv_bfloat16 l0 = __float2bfloat16_rn(r0);
    __nv_bfloat16 l1 = __float2bfloat16_rn(r1);
    hi = (uint32_t)__bfloat16_as_ushort(h0) | ((uint32_t)__bfloat16_as_ushort(h1) << 16);
    lo = (uint32_t)__bfloat16_as_ushort(l0) | ((uint32_t)__bfloat16_as_ushort(l1) << 16);
}

// ---------------------------------------------------------------------------
// Kernel 1: per-batch best car prior -> decode -> clip -> boxes/valid + bins
// ---------------------------------------------------------------------------
__global__ void best_prior_kernel(const float* __restrict__ loc,
                                  const float* __restrict__ conf,
                                  const float* __restrict__ priors,
                                  float* __restrict__ out)
{
    int b = blockIdx.x, tid = threadIdx.x;
    const float2* cb = (const float2*)(conf + (size_t)b * N_ * 2);

    float best = -FLT_MAX;
    int   bidx = 0x7fffffff;
    int   anyc = 0;

    for (int i = tid; i < N_; i += 256) {
        float2 c = cb[i];
        if (c.y > c.x) {
            anyc = 1;
            float p1 = 1.0f / (1.0f + expf(c.x - c.y));
            if (p1 > best || (p1 == best && i < bidx)) { best = p1; bidx = i; }
        }
    }

    int has = __syncthreads_or(anyc);

    __shared__ float sv[256];
    __shared__ int   si[256];
    sv[tid] = best; si[tid] = bidx;
    __syncthreads();
    for (int s = 128; s > 0; s >>= 1) {
        if (tid < s) {
            float v2 = sv[tid+s]; int i2 = si[tid+s];
            if (v2 > sv[tid] || (v2 == sv[tid] && i2 < si[tid])) { sv[tid]=v2; si[tid]=i2; }
        }
        __syncthreads();
    }

    if (tid == 0) {
        float bx0=0.f,bx1=0.f,bx2=0.f,bx3=0.f;
        int v = 0;
        int n0=0,n1=0,n2=0,n3=0;
        if (has) {
            int idx = si[0];
            float p0 = priors[4*idx+0], p1p = priors[4*idx+1];
            float p2 = priors[4*idx+2], p3  = priors[4*idx+3];
            const float* l = loc + ((size_t)b * N_ + idx) * 4;
            float cx = p0 + l[0] * 0.1f * p2;
            float cy = p1p + l[1] * 0.1f * p3;
            float w  = p2 * expf(l[2] * 0.2f);
            float h  = p3 * expf(l[3] * 0.2f);
            float x1 = cx - 0.5f*w, y1 = cy - 0.5f*h;
            float x2 = x1 + w,      y2 = y1 + h;
            v = (x2 > x1) && (y2 > y1);
            bx0 = fminf(fmaxf(x1, 0.f), 1.f);
            bx1 = fminf(fmaxf(y1, 0.f), 1.f);
            bx2 = fminf(fmaxf(x2, 0.f), 1.f);
            bx3 = fminf(fmaxf(y2, 0.f), 1.f);
            const float step = (float)(300.0 / 19.0);
            float t;
            t = fminf(fmaxf(bx0*300.0f,0.f),300.f)/step; n0 = (int)floorf(fminf(fmaxf(t,0.f),18.f));
            t = fminf(fmaxf(bx1*300.0f,0.f),300.f)/step; n1 = (int)floorf(fminf(fmaxf(t,0.f),18.f));
            t = fminf(fmaxf(bx2*300.0f,0.f),300.f)/step; n2 = (int)floorf(fminf(fmaxf(t,0.f),18.f));
            t = fminf(fmaxf(bx3*300.0f,0.f),300.f)/step; n3 = (int)floorf(fminf(fmaxf(t,0.f),18.f));
        }
        out[2432 + b*4 + 0] = bx0;
        out[2432 + b*4 + 1] = bx1;
        out[2432 + b*4 + 2] = bx2;
        out[2432 + b*4 + 3] = bx3;
        out[2944 + b] = v ? 1.0f : 0.0f;
        g_valid[b]   = v;
        g_bins[b*4+0] = n0; g_bins[b*4+1] = n1;
        g_bins[b*4+2] = n2; g_bins[b*4+3] = n3;
    }
}

// ---------------------------------------------------------------------------
// Kernel 2: masked global max pool -> g_feat [B, C]
// coalesced full-channel scan (361 contiguous floats), mask in registers
// ---------------------------------------------------------------------------
__global__ void extract_kernel(const float* __restrict__ feats)
{
    int b    = blockIdx.x;
    int warp = threadIdx.x >> 5;
    int lane = threadIdx.x & 31;
    int c    = blockIdx.y * 8 + warp;

    if (!g_valid[b]) { if (lane == 0) g_feat[b*C_ + c] = 0.f; return; }

    int x1 = g_bins[b*4+0], y1 = g_bins[b*4+1];
    int x2 = g_bins[b*4+2], y2 = g_bins[b*4+3];

    const float* f = feats + ((size_t)(b * C_ + c)) * (H_ * H_);
    float m = -FLT_MAX;
    for (int t = lane; t < H_ * H_; t += 32) {
        float v = f[t];
        int y = t / H_;
        int x = t - y * H_;
        bool in = (y >= y1) & (y <= y2) & (x >= x1) & (x <= x2);
        m = fmaxf(m, in ? v : -FLT_MAX);
    }
    #pragma unroll
    for (int o = 16; o; o >>= 1) m = fmaxf(m, __shfl_xor_sync(0xffffffffu, m, o));
    if (lane == 0) g_feat[b*C_ + c] = m;
}

// ---------------------------------------------------------------------------
// Kernel 3: bf16-3x mma.sync GEMM, split-K, double-buffered pre-split SMEM.
//   part[split][128][HID_] = A[128, Ktot] @ Bw[Ktot, HID_]
//   BM=128, BN=64, BK=32; 8 warps, warp tile 32x32.
//   SMEM holds bf16x2-packed hi/lo planes (k-pairs packed per u32).
// ---------------------------------------------------------------------------
#define APITCH 20      // u32 per A row (16 data + 4 pad)
#define BPITCH 72      // u32 per B k'-row (64 data + 8 pad)
#define A_SZ   (128*APITCH)          // 2560
#define B_SZ   (16*BPITCH)           // 1152
#define BUFSZ  (2*A_SZ + 2*B_SZ)     // 7424 u32 = 29696 B

__global__ __launch_bounds__(256, 2)
void gemm_bf16_kernel(int Ktot, int KSPLIT,
                      const float* __restrict__ A, const float* __restrict__ Bw,
                      float* __restrict__ part)
{
    extern __shared__ uint32_t sm[];

    const int tid  = threadIdx.x;
    const int wid  = tid >> 5;
    const int lane = tid & 31;
    const int gid  = lane >> 2;      // 0..7
    const int tig  = lane & 3;       // 0..3
    const int n0   = blockIdx.x * 64;
    const int ks   = blockIdx.y * KSPLIT;
    const int NCH  = KSPLIT >> 5;
    const int mbase = (wid & 3) * 32;
    const int nbase = (wid >> 2) * 32;

    // B staging coords: each thread owns one (p, nq): rows 2p,2p+1, cols nq*4..+3
    const int bp_p  = tid >> 4;      // 0..15  (k-pair index)
    const int bp_nq = tid & 15;      // 0..15  (float4 column quad)

    float acc[2][4][4];
    #pragma unroll
    for (int i = 0; i < 2; i++)
        #pragma unroll
        for (int j = 0; j < 4; j++)
            #pragma unroll
            for (int q = 0; q < 4; q++) acc[i][j][q] = 0.f;

    float4 ra[4];        // A: 4 float4 per thread (128x32 chunk)
    float4 rb0, rb1;     // B: rows 2p and 2p+1, one float4 each

    // ---- register load of chunk at k0 ----
    #define LOAD_REGS(k0) do {                                              \
        _Pragma("unroll")                                                   \
        for (int j = 0; j < 4; j++) {                                       \
            int f4 = tid + j * 256;                                         \
            int row = f4 >> 3, q = f4 & 7;                                  \
            ra[j] = *(const float4*)(A + (size_t)row * Ktot + (k0) + q * 4);\
        }                                                                   \
        {                                                                   \
            const float* bp = Bw + (size_t)((k0) + 2 * bp_p) * HID_         \
                              + n0 + bp_nq * 4;                             \
            rb0 = *(const float4*)bp;                                       \
            rb1 = *(const float4*)(bp + HID_);                              \
        }                                                                   \
    } while (0)

    // ---- split+pack registers into SMEM buffer ----
    #define STORE_SMEM(buf) do {                                            \
        uint32_t* Ah = sm + (buf) * BUFSZ;                                  \
        uint32_t* Al = Ah + A_SZ;                                           \
        uint32_t* Bh = Ah + 2 * A_SZ;                                       \
        uint32_t* Bl = Bh + B_SZ;                                           \
        _Pragma("unroll")                                                   \
        for (int j = 0; j < 4; j++) {                                       \
            int f4 = tid + j * 256;                                         \
            int row = f4 >> 3, q = f4 & 7;                                  \
            uint32_t h0, l0, h1, l1;                                        \
            split_pack(ra[j].x, ra[j].y, h0, l0);                           \
            split_pack(ra[j].z, ra[j].w, h1, l1);                           \
            *(uint2*)&Ah[row * APITCH + q * 2] = make_uint2(h0, h1);        \
            *(uint2*)&Al[row * APITCH + q * 2] = make_uint2(l0, l1);        \
        }                                                                   \
        {                                                                   \
            uint32_t h0,l0,h1,l1,h2,l2,h3,l3;                               \
            split_pack(rb0.x, rb1.x, h0, l0);                               \
            split_pack(rb0.y, rb1.y, h1, l1);                               \
            split_pack(rb0.z, rb1.z, h2, l2);                               \
            split_pack(rb0.w, rb1.w, h3, l3);                               \
            *(uint4*)&Bh[bp_p * BPITCH + bp_nq * 4] = make_uint4(h0,h1,h2,h3); \
            *(uint4*)&Bl[bp_p * BPITCH + bp_nq * 4] = make_uint4(l0,l1,l2,l3); \
        }                                                                   \
    } while (0)

    LOAD_REGS(ks);
    STORE_SMEM(0);
    if (NCH > 1) LOAD_REGS(ks + 32);
    __syncthreads();

    for (int c = 0; c < NCH; c++) {
        const int buf = c & 1;
        const uint32_t* Ah = sm + buf * BUFSZ;
        const uint32_t* Al = Ah + A_SZ;
        const uint32_t* Bh = Ah + 2 * A_SZ;
        const uint32_t* Bl = Bh + B_SZ;

        #pragma unroll
        for (int s = 0; s < 2; s++) {
            uint32_t bh[4][2], bl[4][2];
            const int kb = s * 8 + tig;
            #pragma unroll
            for (int nt = 0; nt < 4; nt++) {
                int col = nbase + nt * 8 + gid;
                bh[nt][0] = Bh[kb * BPITCH + col];
                bh[nt][1] = Bh[(kb + 4) * BPITCH + col];
                bl[nt][0] = Bl[kb * BPITCH + col];
                bl[nt][1] = Bl[(kb + 4) * BPITCH + col];
            }
            #pragma unroll
            for (int mt = 0; mt < 2; mt++) {
                int r = mbase + mt * 16 + gid;
                int base = r * APITCH + s * 8 + tig;
                uint32_t ah[4], al[4];
                ah[0] = Ah[base];                 ah[1] = Ah[base + 8 * APITCH];
                ah[2] = Ah[base + 4];             ah[3] = Ah[base + 8 * APITCH + 4];
                al[0] = Al[base];                 al[1] = Al[base + 8 * APITCH];
                al[2] = Al[base + 4];             al[3] = Al[base + 8 * APITCH + 4];
                #pragma unroll
                for (int nt = 0; nt < 4; nt++) {
                    MMA_BF16(acc[mt][nt], ah, bh[nt][0], bh[nt][1]);
                    MMA_BF16(acc[mt][nt], ah, bl[nt][0], bl[nt][1]);
                    MMA_BF16(acc[mt][nt], al, bh[nt][0], bh[nt][1]);
                }
            }
        }

        if (c + 1 < NCH) STORE_SMEM(buf ^ 1);
        if (c + 2 < NCH) LOAD_REGS(ks + (c + 2) * 32);
        __syncthreads();
    }

    // epilogue: partial sums
    #pragma unroll
    for (int mt = 0; mt < 2; mt++) {
        int row = mbase + mt * 16 + gid;
        float* base = part + ((size_t)blockIdx.y * 128 + row) * HID_ + n0 + nbase;
        #pragma unroll
        for (int nt = 0; nt < 4; nt++) {
            float* d = base + nt * 8 + tig * 2;
            *(float2*)d               = make_float2(acc[mt][nt][0], acc[mt][nt][1]);
            *(float2*)(d + 8 * HID_)  = make_float2(acc[mt][nt][2], acc[mt][nt][3]);
        }
    }
    #undef LOAD_REGS
    #undef STORE_SMEM
}

// ---------------------------------------------------------------------------
// Kernel 4: split-K reduce + bias + relu
// ---------------------------------------------------------------------------
template<bool RELU>
__global__ void reduce_bias_kernel(int S, const float* __restrict__ part,
                                   const float* __restrict__ bias,
                                   float* __restrict__ out)
{
    int i4 = blockIdx.x * 256 + threadIdx.x;
    const int MN = B_ * HID_;
    int base = i4 * 4;
    if (base >= MN) return;
    float4 s = make_float4(0.f, 0.f, 0.f, 0.f);
    for (int p = 0; p < S; p++) {
        float4 v = *(const float4*)(part + (size_t)p * MN + base);
        s.x += v.x; s.y += v.y; s.z += v.z; s.w += v.w;
    }
    int n = base & (HID_ - 1);
    s.x += bias[n + 0]; s.y += bias[n + 1]; s.z += bias[n + 2]; s.w += bias[n + 3];
    if (RELU) {
        s.x = fmaxf(s.x, 0.f); s.y = fmaxf(s.y, 0.f);
        s.z = fmaxf(s.z, 0.f); s.w = fmaxf(s.w, 0.f);
    }
    *(float4*)(out + base) = s;
}

// ---------------------------------------------------------------------------
// Kernel 5: final FC  out[B,19] = h2 @ w3 + b3
// ---------------------------------------------------------------------------
__global__ void fc3_kernel(const float* __restrict__ A, const float* __restrict__ W,
                           const float* __restrict__ bias, float* __restrict__ out)
{
    int b = blockIdx.x;
    int tid = threadIdx.x, warp = tid >> 5, lane = tid & 31;
    __shared__ float sh[HID_];
    const float* a = A + (size_t)b * HID_;
    for (int i = tid; i < HID_; i += 256) sh[i] = a[i];
    __syncthreads();
    for (int col = warp; col < FG_; col += 8) {
        float s = 0.f;
        for (int k = lane; k < HID_; k += 32) s += sh[k] * W[(size_t)k * FG_ + col];
        #pragma unroll
        for (int o = 16; o; o >>= 1) s += __shfl_xor_sync(0xffffffffu, s, o);
        if (lane == 0) out[b * FG_ + col] = s + bias[col];
    }
}

// ---------------------------------------------------------------------------
extern "C" void kernel_launch(void* const* d_in, const int* in_sizes, int n_in,
                              void* d_out, int out_size)
{
    const float* loc      = (const float*)d_in[0];
    const float* conf     = (const float*)d_in[1];
    const float* priors   = (const float*)d_in[2];
    const float* features = (const float*)d_in[3];
    const float* w1 = (const float*)d_in[4];
    const float* b1 = (const float*)d_in[5];
    const float* w2 = (const float*)d_in[6];
    const float* b2 = (const float*)d_in[7];
    const float* w3 = (const float*)d_in[8];
    const float* b3 = (const float*)d_in[9];
    float* out = (float*)d_out;

    void *pf, *p1, *p2, *ppart;
    cudaGetSymbolAddress(&pf,    g_feat);
    cudaGetSymbolAddress(&p1,    g_h1);
    cudaGetSymbolAddress(&p2,    g_h2);
    cudaGetSymbolAddress(&ppart, g_part);

    const int SMEM = 2 * BUFSZ * 4;   // 59392 B
    cudaFuncSetAttribute(gemm_bf16_kernel,
                         cudaFuncAttributeMaxDynamicSharedMemorySize, SMEM);

    best_prior_kernel<<<B_, 256>>>(loc, conf, priors, out);
    extract_kernel<<<dim3(B_, C_/8), 256>>>(features);

    // GEMM1: [128,512] @ [512,4096], split-K=4 (KSPLIT=128, NCH=4)
    gemm_bf16_kernel<<<dim3(HID_/64, 4), 256, SMEM>>>(C_, 128,
        (const float*)pf, w1, (float*)ppart);
    reduce_bias_kernel<true><<<(B_*HID_/4 + 255)/256, 256>>>(4,
        (const float*)ppart, b1, (float*)p1);

    // GEMM2: [128,4096] @ [4096,4096], split-K=4 (KSPLIT=1024, NCH=32)
    gemm_bf16_kernel<<<dim3(HID_/64, 4), 256, SMEM>>>(HID_, 1024,
        (const float*)p1, w2, (float*)ppart);
    reduce_bias_kernel<true><<<(B_*HID_/4 + 255)/256, 256>>>(4,
        (const float*)ppart, b2, (float*)p2);

    fc3_kernel<<<B_, 256>>>((const float*)p2, w3, b3, out);
}

// round 7
// speedup vs baseline: 2.5336x; 1.1003x over previous
#include <cuda_runtime.h>
#include <cuda_fp16.h>
#include <math.h>
#include <cfloat>
#include <cstdint>

#define B_   128
#define N_   8732
#define C_   512
#define H_   19
#define FG_  19
#define HID_ 4096

// ---------------------------------------------------------------------------
// scratch (device globals — no allocation allowed)
// ---------------------------------------------------------------------------
__device__ float g_feat[B_*C_];
__device__ float g_h1[B_*HID_];
__device__ float g_h2[B_*HID_];
__device__ int   g_bins[B_*4];
__device__ int   g_valid[B_];
__device__ float g_part[8*B_*HID_];     // split-K partials (S<=8)

// ---------------------------------------------------------------------------
// helpers
// ---------------------------------------------------------------------------
#define MMA_F16(c, a, b0, b1)                                               \
    asm volatile("mma.sync.aligned.m16n8k16.row.col.f32.f16.f16.f32 "       \
        "{%0,%1,%2,%3}, {%4,%5,%6,%7}, {%8,%9}, {%0,%1,%2,%3};"             \
        : "+f"((c)[0]), "+f"((c)[1]), "+f"((c)[2]), "+f"((c)[3])            \
        : "r"((a)[0]), "r"((a)[1]), "r"((a)[2]), "r"((a)[3]),               \
          "r"(b0), "r"(b1))

__device__ __forceinline__ uint32_t pack2_f16(float x0, float x1)
{
    __half2 h = __floats2half2_rn(x0, x1);
    return *(uint32_t*)&h;
}

// split pair (x0,x1) into f16 hi/lo planes, packed f16x2 (x0 in low half)
__device__ __forceinline__ void split_pack_f16(float x0, float x1,
                                               uint32_t& hi, uint32_t& lo)
{
    __half h0 = __float2half_rn(x0);
    __half h1 = __float2half_rn(x1);
    float r0 = x0 - __half2float(h0);
    float r1 = x1 - __half2float(h1);
    __half l0 = __float2half_rn(r0);
    __half l1 = __float2half_rn(r1);
    hi = (uint32_t)__half_as_ushort(h0) | ((uint32_t)__half_as_ushort(h1) << 16);
    lo = (uint32_t)__half_as_ushort(l0) | ((uint32_t)__half_as_ushort(l1) << 16);
}

// ---------------------------------------------------------------------------
// Kernel 1: per-batch best car prior -> decode -> clip -> boxes/valid + bins
// ---------------------------------------------------------------------------
__global__ void best_prior_kernel(const float* __restrict__ loc,
                                  const float* __restrict__ conf,
                                  const float* __restrict__ priors,
                                  float* __restrict__ out)
{
    int b = blockIdx.x, tid = threadIdx.x;
    const float2* cb = (const float2*)(conf + (size_t)b * N_ * 2);

    float best = -FLT_MAX;
    int   bidx = 0x7fffffff;
    int   anyc = 0;

    for (int i = tid; i < N_; i += 256) {
        float2 c = cb[i];
        if (c.y > c.x) {
            anyc = 1;
            float p1 = 1.0f / (1.0f + expf(c.x - c.y));
            if (p1 > best || (p1 == best && i < bidx)) { best = p1; bidx = i; }
        }
    }

    int has = __syncthreads_or(anyc);

    __shared__ float sv[256];
    __shared__ int   si[256];
    sv[tid] = best; si[tid] = bidx;
    __syncthreads();
    for (int s = 128; s > 0; s >>= 1) {
        if (tid < s) {
            float v2 = sv[tid+s]; int i2 = si[tid+s];
            if (v2 > sv[tid] || (v2 == sv[tid] && i2 < si[tid])) { sv[tid]=v2; si[tid]=i2; }
        }
        __syncthreads();
    }

    if (tid == 0) {
        float bx0=0.f,bx1=0.f,bx2=0.f,bx3=0.f;
        int v = 0;
        int n0=0,n1=0,n2=0,n3=0;
        if (has) {
            int idx = si[0];
            float p0 = priors[4*idx+0], p1p = priors[4*idx+1];
            float p2 = priors[4*idx+2], p3  = priors[4*idx+3];
            const float* l = loc + ((size_t)b * N_ + idx) * 4;
            float cx = p0 + l[0] * 0.1f * p2;
            float cy = p1p + l[1] * 0.1f * p3;
            float w  = p2 * expf(l[2] * 0.2f);
            float h  = p3 * expf(l[3] * 0.2f);
            float x1 = cx - 0.5f*w, y1 = cy - 0.5f*h;
            float x2 = x1 + w,      y2 = y1 + h;
            v = (x2 > x1) && (y2 > y1);
            bx0 = fminf(fmaxf(x1, 0.f), 1.f);
            bx1 = fminf(fmaxf(y1, 0.f), 1.f);
            bx2 = fminf(fmaxf(x2, 0.f), 1.f);
            bx3 = fminf(fmaxf(y2, 0.f), 1.f);
            const float step = (float)(300.0 / 19.0);
            float t;
            t = fminf(fmaxf(bx0*300.0f,0.f),300.f)/step; n0 = (int)floorf(fminf(fmaxf(t,0.f),18.f));
            t = fminf(fmaxf(bx1*300.0f,0.f),300.f)/step; n1 = (int)floorf(fminf(fmaxf(t,0.f),18.f));
            t = fminf(fmaxf(bx2*300.0f,0.f),300.f)/step; n2 = (int)floorf(fminf(fmaxf(t,0.f),18.f));
            t = fminf(fmaxf(bx3*300.0f,0.f),300.f)/step; n3 = (int)floorf(fminf(fmaxf(t,0.f),18.f));
        }
        out[2432 + b*4 + 0] = bx0;
        out[2432 + b*4 + 1] = bx1;
        out[2432 + b*4 + 2] = bx2;
        out[2432 + b*4 + 3] = bx3;
        out[2944 + b] = v ? 1.0f : 0.0f;
        g_valid[b]   = v;
        g_bins[b*4+0] = n0; g_bins[b*4+1] = n1;
        g_bins[b*4+2] = n2; g_bins[b*4+3] = n3;
    }
}

// ---------------------------------------------------------------------------
// Kernel 2: masked global max pool -> g_feat [B, C]  (coalesced channel scan)
// ---------------------------------------------------------------------------
__global__ void extract_kernel(const float* __restrict__ feats)
{
    int b    = blockIdx.x;
    int warp = threadIdx.x >> 5;
    int lane = threadIdx.x & 31;
    int c    = blockIdx.y * 8 + warp;

    if (!g_valid[b]) { if (lane == 0) g_feat[b*C_ + c] = 0.f; return; }

    int x1 = g_bins[b*4+0], y1 = g_bins[b*4+1];
    int x2 = g_bins[b*4+2], y2 = g_bins[b*4+3];

    const float* f = feats + ((size_t)(b * C_ + c)) * (H_ * H_);
    float m = -FLT_MAX;
    for (int t = lane; t < H_ * H_; t += 32) {
        float v = f[t];
        int y = t / H_;
        int x = t - y * H_;
        bool in = (y >= y1) & (y <= y2) & (x >= x1) & (x <= x2);
        m = fmaxf(m, in ? v : -FLT_MAX);
    }
    #pragma unroll
    for (int o = 16; o; o >>= 1) m = fmaxf(m, __shfl_xor_sync(0xffffffffu, m, o));
    if (lane == 0) g_feat[b*C_ + c] = m;
}

// ---------------------------------------------------------------------------
// Kernel 3: fp16 2-term mma.sync GEMM, split-K, double-buffered SMEM.
//   part[split][128][HID_] = A[128, Ktot] @ Bw[Ktot, HID_]
//   Result = f16(A) * (Bhi + Blo) : 2 MMAs per unit tile (vs 3 in bf16-3x).
//   BM=128, BN=64, BK=32; 8 warps, warp tile 32x32.
// ---------------------------------------------------------------------------
#define APITCH 20      // u32 per A row (16 data + 4 pad)
#define BPITCH 72      // u32 per B k-pair row (64 data + 8 pad)
#define A_SZ   (128*APITCH)          // 2560 u32
#define B_SZ   (16*BPITCH)           // 1152 u32
#define BUFSZ  (A_SZ + 2*B_SZ)       // 4864 u32 = 19456 B

__global__ __launch_bounds__(256, 2)
void gemm_f16_kernel(int Ktot, int KSPLIT,
                     const float* __restrict__ A, const float* __restrict__ Bw,
                     float* __restrict__ part)
{
    extern __shared__ uint32_t sm[];

    const int tid  = threadIdx.x;
    const int wid  = tid >> 5;
    const int lane = tid & 31;
    const int gid  = lane >> 2;      // 0..7
    const int tig  = lane & 3;       // 0..3
    const int n0   = blockIdx.x * 64;
    const int ks   = blockIdx.y * KSPLIT;
    const int NCH  = KSPLIT >> 5;
    const int mbase = (wid & 3) * 32;
    const int nbase = (wid >> 2) * 32;

    // B staging: thread owns (p, nq): k rows 2p,2p+1, col quad nq*4..+3
    const int bp_p  = tid >> 4;      // 0..15
    const int bp_nq = tid & 15;      // 0..15

    float acc[2][4][4];
    #pragma unroll
    for (int i = 0; i < 2; i++)
        #pragma unroll
        for (int j = 0; j < 4; j++)
            #pragma unroll
            for (int q = 0; q < 4; q++) acc[i][j][q] = 0.f;

    float4 ra[4];
    float4 rb0, rb1;

    #define LOAD_REGS(k0) do {                                              \
        _Pragma("unroll")                                                   \
        for (int j = 0; j < 4; j++) {                                       \
            int f4 = tid + j * 256;                                         \
            int row = f4 >> 3, q = f4 & 7;                                  \
            ra[j] = *(const float4*)(A + (size_t)row * Ktot + (k0) + q * 4);\
        }                                                                   \
        {                                                                   \
            const float* bp = Bw + (size_t)((k0) + 2 * bp_p) * HID_         \
                              + n0 + bp_nq * 4;                             \
            rb0 = *(const float4*)bp;                                       \
            rb1 = *(const float4*)(bp + HID_);                              \
        }                                                                   \
    } while (0)

    #define STORE_SMEM(buf) do {                                            \
        uint32_t* Ah = sm + (buf) * BUFSZ;                                  \
        uint32_t* Bh = Ah + A_SZ;                                           \
        uint32_t* Bl = Bh + B_SZ;                                           \
        _Pragma("unroll")                                                   \
        for (int j = 0; j < 4; j++) {                                       \
            int f4 = tid + j * 256;                                         \
            int row = f4 >> 3, q = f4 & 7;                                  \
            uint32_t h0 = pack2_f16(ra[j].x, ra[j].y);                      \
            uint32_t h1 = pack2_f16(ra[j].z, ra[j].w);                      \
            *(uint2*)&Ah[row * APITCH + q * 2] = make_uint2(h0, h1);        \
        }                                                                   \
        {                                                                   \
            uint32_t h0,l0,h1,l1,h2,l2,h3,l3;                               \
            split_pack_f16(rb0.x, rb1.x, h0, l0);                           \
            split_pack_f16(rb0.y, rb1.y, h1, l1);                           \
            split_pack_f16(rb0.z, rb1.z, h2, l2);                           \
            split_pack_f16(rb0.w, rb1.w, h3, l3);                           \
            *(uint4*)&Bh[bp_p * BPITCH + bp_nq * 4] = make_uint4(h0,h1,h2,h3); \
            *(uint4*)&Bl[bp_p * BPITCH + bp_nq * 4] = make_uint4(l0,l1,l2,l3); \
        }                                                                   \
    } while (0)

    LOAD_REGS(ks);
    STORE_SMEM(0);
    if (NCH > 1) LOAD_REGS(ks + 32);
    __syncthreads();

    for (int c = 0; c < NCH; c++) {
        const int buf = c & 1;
        const uint32_t* Ah = sm + buf * BUFSZ;
        const uint32_t* Bh = Ah + A_SZ;
        const uint32_t* Bl = Bh + B_SZ;

        #pragma unroll
        for (int s = 0; s < 2; s++) {
            uint32_t bh[4][2], bl[4][2];
            const int kb = s * 8 + tig;
            #pragma unroll
            for (int nt = 0; nt < 4; nt++) {
                int col = nbase + nt * 8 + gid;
                bh[nt][0] = Bh[kb * BPITCH + col];
                bh[nt][1] = Bh[(kb + 4) * BPITCH + col];
                bl[nt][0] = Bl[kb * BPITCH + col];
                bl[nt][1] = Bl[(kb + 4) * BPITCH + col];
            }
            #pragma unroll
            for (int mt = 0; mt < 2; mt++) {
                int r = mbase + mt * 16 + gid;
                int base = r * APITCH + s * 8 + tig;
                uint32_t ah[4];
                ah[0] = Ah[base];        ah[1] = Ah[base + 8 * APITCH];
                ah[2] = Ah[base + 4];    ah[3] = Ah[base + 8 * APITCH + 4];
                #pragma unroll
                for (int nt = 0; nt < 4; nt++) {
                    MMA_F16(acc[mt][nt], ah, bh[nt][0], bh[nt][1]);
                    MMA_F16(acc[mt][nt], ah, bl[nt][0], bl[nt][1]);
                }
            }
        }

        if (c + 1 < NCH) STORE_SMEM(buf ^ 1);
        if (c + 2 < NCH) LOAD_REGS(ks + (c + 2) * 32);
        __syncthreads();
    }

    // epilogue: partial sums
    #pragma unroll
    for (int mt = 0; mt < 2; mt++) {
        int row = mbase + mt * 16 + gid;
        float* base = part + ((size_t)blockIdx.y * 128 + row) * HID_ + n0 + nbase;
        #pragma unroll
        for (int nt = 0; nt < 4; nt++) {
            float* d = base + nt * 8 + tig * 2;
            *(float2*)d               = make_float2(acc[mt][nt][0], acc[mt][nt][1]);
            *(float2*)(d + 8 * HID_)  = make_float2(acc[mt][nt][2], acc[mt][nt][3]);
        }
    }
    #undef LOAD_REGS
    #undef STORE_SMEM
}

// ---------------------------------------------------------------------------
// Kernel 4: split-K reduce + bias + relu
// ---------------------------------------------------------------------------
template<bool RELU>
__global__ void reduce_bias_kernel(int S, const float* __restrict__ part,
                                   const float* __restrict__ bias,
                                   float* __restrict__ out)
{
    int i4 = blockIdx.x * 256 + threadIdx.x;
    const int MN = B_ * HID_;
    int base = i4 * 4;
    if (base >= MN) return;
    float4 s = make_float4(0.f, 0.f, 0.f, 0.f);
    for (int p = 0; p < S; p++) {
        float4 v = *(const float4*)(part + (size_t)p * MN + base);
        s.x += v.x; s.y += v.y; s.z += v.z; s.w += v.w;
    }
    int n = base & (HID_ - 1);
    s.x += bias[n + 0]; s.y += bias[n + 1]; s.z += bias[n + 2]; s.w += bias[n + 3];
    if (RELU) {
        s.x = fmaxf(s.x, 0.f); s.y = fmaxf(s.y, 0.f);
        s.z = fmaxf(s.z, 0.f); s.w = fmaxf(s.w, 0.f);
    }
    *(float4*)(out + base) = s;
}

// ---------------------------------------------------------------------------
// Kernel 5: final FC  out[B,19] = h2 @ w3 + b3
// ---------------------------------------------------------------------------
__global__ void fc3_kernel(const float* __restrict__ A, const float* __restrict__ W,
                           const float* __restrict__ bias, float* __restrict__ out)
{
    int b = blockIdx.x;
    int tid = threadIdx.x, warp = tid >> 5, lane = tid & 31;
    __shared__ float sh[HID_];
    const float* a = A + (size_t)b * HID_;
    for (int i = tid; i < HID_; i += 256) sh[i] = a[i];
    __syncthreads();
    for (int col = warp; col < FG_; col += 8) {
        float s = 0.f;
        for (int k = lane; k < HID_; k += 32) s += sh[k] * W[(size_t)k * FG_ + col];
        #pragma unroll
        for (int o = 16; o; o >>= 1) s += __shfl_xor_sync(0xffffffffu, s, o);
        if (lane == 0) out[b * FG_ + col] = s + bias[col];
    }
}

// no-op spacer so ncu's "-s 5 -c 1" lands on GEMM2 (launch #6)
__global__ void noop_kernel() {}

// ---------------------------------------------------------------------------
extern "C" void kernel_launch(void* const* d_in, const int* in_sizes, int n_in,
                              void* d_out, int out_size)
{
    const float* loc      = (const float*)d_in[0];
    const float* conf     = (const float*)d_in[1];
    const float* priors   = (const float*)d_in[2];
    const float* features = (const float*)d_in[3];
    const float* w1 = (const float*)d_in[4];
    const float* b1 = (const float*)d_in[5];
    const float* w2 = (const float*)d_in[6];
    const float* b2 = (const float*)d_in[7];
    const float* w3 = (const float*)d_in[8];
    const float* b3 = (const float*)d_in[9];
    float* out = (float*)d_out;

    void *pf, *p1, *p2, *ppart;
    cudaGetSymbolAddress(&pf,    g_feat);
    cudaGetSymbolAddress(&p1,    g_h1);
    cudaGetSymbolAddress(&p2,    g_h2);
    cudaGetSymbolAddress(&ppart, g_part);

    const int SMEM = 2 * BUFSZ * 4;   // 38912 B
    cudaFuncSetAttribute(gemm_f16_kernel,
                         cudaFuncAttributeMaxDynamicSharedMemorySize, SMEM);

    best_prior_kernel<<<B_, 256>>>(loc, conf, priors, out);           // 1
    extract_kernel<<<dim3(B_, C_/8), 256>>>(features);                // 2

    // GEMM1: [128,512] @ [512,4096], split-K=4 (KSPLIT=128, NCH=4)
    gemm_f16_kernel<<<dim3(HID_/64, 4), 256, SMEM>>>(C_, 128,         // 3
        (const float*)pf, w1, (float*)ppart);
    reduce_bias_kernel<true><<<(B_*HID_/4 + 255)/256, 256>>>(4,       // 4
        (const float*)ppart, b1, (float*)p1);

    noop_kernel<<<1, 32>>>();                                         // 5

    // GEMM2: [128,4096] @ [4096,4096], split-K=8 (KSPLIT=512, NCH=16)
    gemm_f16_kernel<<<dim3(HID_/64, 8), 256, SMEM>>>(HID_, 512,       // 6 (profiled)
        (const float*)p1, w2, (float*)ppart);
    reduce_bias_kernel<true><<<(B_*HID_/4 + 255)/256, 256>>>(8,       // 7
        (const float*)ppart, b2, (float*)p2);

    fc3_kernel<<<B_, 256>>>((const float*)p2, w3, b3, out);           // 8
}

// round 8
// speedup vs baseline: 2.6731x; 1.0551x over previous
#include <cuda_runtime.h>
#include <cuda_fp16.h>
#include <math.h>
#include <cfloat>
#include <cstdint>

#define B_   128
#define N_   8732
#define C_   512
#define H_   19
#define FG_  19
#define HID_ 4096

// ---------------------------------------------------------------------------
// scratch (device globals — no allocation allowed)
// ---------------------------------------------------------------------------
__device__ float g_feat[B_*C_];
__device__ float g_h1[B_*HID_];
__device__ float g_h2[B_*HID_];
__device__ int   g_bins[B_*4];
__device__ int   g_valid[B_];
__device__ float g_part[4*B_*HID_];     // split-K partials (S<=4)

// ---------------------------------------------------------------------------
// helpers
// ---------------------------------------------------------------------------
#define MMA_F16(c, a, b0, b1)                                               \
    asm volatile("mma.sync.aligned.m16n8k16.row.col.f32.f16.f16.f32 "       \
        "{%0,%1,%2,%3}, {%4,%5,%6,%7}, {%8,%9}, {%0,%1,%2,%3};"             \
        : "+f"((c)[0]), "+f"((c)[1]), "+f"((c)[2]), "+f"((c)[3])            \
        : "r"((a)[0]), "r"((a)[1]), "r"((a)[2]), "r"((a)[3]),               \
          "r"(b0), "r"(b1))

#define LDSM_X4(r, addr)                                                    \
    asm volatile("ldmatrix.sync.aligned.m8n8.x4.shared.b16 "                \
        "{%0,%1,%2,%3}, [%4];"                                              \
        : "=r"((r)[0]), "=r"((r)[1]), "=r"((r)[2]), "=r"((r)[3])            \
        : "r"(addr) : "memory")

#define LDSM_X4T(r, addr)                                                   \
    asm volatile("ldmatrix.sync.aligned.m8n8.x4.trans.shared.b16 "          \
        "{%0,%1,%2,%3}, [%4];"                                              \
        : "=r"((r)[0]), "=r"((r)[1]), "=r"((r)[2]), "=r"((r)[3])            \
        : "r"(addr) : "memory")

__device__ __forceinline__ uint32_t pack2_f16(float x0, float x1)
{
    __half2 h = __floats2half2_rn(x0, x1);
    return *(uint32_t*)&h;
}

// split pair (x0,x1) into f16 hi/lo, packed f16x2 (x0 in low half)
__device__ __forceinline__ void split_pack_f16(float x0, float x1,
                                               uint32_t& hi, uint32_t& lo)
{
    __half h0 = __float2half_rn(x0);
    __half h1 = __float2half_rn(x1);
    float r0 = x0 - __half2float(h0);
    float r1 = x1 - __half2float(h1);
    __half l0 = __float2half_rn(r0);
    __half l1 = __float2half_rn(r1);
    hi = (uint32_t)__half_as_ushort(h0) | ((uint32_t)__half_as_ushort(h1) << 16);
    lo = (uint32_t)__half_as_ushort(l0) | ((uint32_t)__half_as_ushort(l1) << 16);
}

// ---------------------------------------------------------------------------
// Kernel 1: per-batch best car prior -> decode -> clip -> boxes/valid + bins
// ---------------------------------------------------------------------------
__global__ void best_prior_kernel(const float* __restrict__ loc,
                                  const float* __restrict__ conf,
                                  const float* __restrict__ priors,
                                  float* __restrict__ out)
{
    int b = blockIdx.x, tid = threadIdx.x;
    const float2* cb = (const float2*)(conf + (size_t)b * N_ * 2);

    float best = -FLT_MAX;
    int   bidx = 0x7fffffff;
    int   anyc = 0;

    for (int i = tid; i < N_; i += 256) {
        float2 c = cb[i];
        if (c.y > c.x) {
            anyc = 1;
            float p1 = 1.0f / (1.0f + expf(c.x - c.y));
            if (p1 > best || (p1 == best && i < bidx)) { best = p1; bidx = i; }
        }
    }

    int has = __syncthreads_or(anyc);

    __shared__ float sv[256];
    __shared__ int   si[256];
    sv[tid] = best; si[tid] = bidx;
    __syncthreads();
    for (int s = 128; s > 0; s >>= 1) {
        if (tid < s) {
            float v2 = sv[tid+s]; int i2 = si[tid+s];
            if (v2 > sv[tid] || (v2 == sv[tid] && i2 < si[tid])) { sv[tid]=v2; si[tid]=i2; }
        }
        __syncthreads();
    }

    if (tid == 0) {
        float bx0=0.f,bx1=0.f,bx2=0.f,bx3=0.f;
        int v = 0;
        int n0=0,n1=0,n2=0,n3=0;
        if (has) {
            int idx = si[0];
            float p0 = priors[4*idx+0], p1p = priors[4*idx+1];
            float p2 = priors[4*idx+2], p3  = priors[4*idx+3];
            const float* l = loc + ((size_t)b * N_ + idx) * 4;
            float cx = p0 + l[0] * 0.1f * p2;
            float cy = p1p + l[1] * 0.1f * p3;
            float w  = p2 * expf(l[2] * 0.2f);
            float h  = p3 * expf(l[3] * 0.2f);
            float x1 = cx - 0.5f*w, y1 = cy - 0.5f*h;
            float x2 = x1 + w,      y2 = y1 + h;
            v = (x2 > x1) && (y2 > y1);
            bx0 = fminf(fmaxf(x1, 0.f), 1.f);
            bx1 = fminf(fmaxf(y1, 0.f), 1.f);
            bx2 = fminf(fmaxf(x2, 0.f), 1.f);
            bx3 = fminf(fmaxf(y2, 0.f), 1.f);
            const float step = (float)(300.0 / 19.0);
            float t;
            t = fminf(fmaxf(bx0*300.0f,0.f),300.f)/step; n0 = (int)floorf(fminf(fmaxf(t,0.f),18.f));
            t = fminf(fmaxf(bx1*300.0f,0.f),300.f)/step; n1 = (int)floorf(fminf(fmaxf(t,0.f),18.f));
            t = fminf(fmaxf(bx2*300.0f,0.f),300.f)/step; n2 = (int)floorf(fminf(fmaxf(t,0.f),18.f));
            t = fminf(fmaxf(bx3*300.0f,0.f),300.f)/step; n3 = (int)floorf(fminf(fmaxf(t,0.f),18.f));
        }
        out[2432 + b*4 + 0] = bx0;
        out[2432 + b*4 + 1] = bx1;
        out[2432 + b*4 + 2] = bx2;
        out[2432 + b*4 + 3] = bx3;
        out[2944 + b] = v ? 1.0f : 0.0f;
        g_valid[b]   = v;
        g_bins[b*4+0] = n0; g_bins[b*4+1] = n1;
        g_bins[b*4+2] = n2; g_bins[b*4+3] = n3;
    }
}

// ---------------------------------------------------------------------------
// Kernel 2: masked global max pool -> g_feat [B, C]  (coalesced channel scan)
// ---------------------------------------------------------------------------
__global__ void extract_kernel(const float* __restrict__ feats)
{
    int b    = blockIdx.x;
    int warp = threadIdx.x >> 5;
    int lane = threadIdx.x & 31;
    int c    = blockIdx.y * 8 + warp;

    if (!g_valid[b]) { if (lane == 0) g_feat[b*C_ + c] = 0.f; return; }

    int x1 = g_bins[b*4+0], y1 = g_bins[b*4+1];
    int x2 = g_bins[b*4+2], y2 = g_bins[b*4+3];

    const float* f = feats + ((size_t)(b * C_ + c)) * (H_ * H_);
    float m = -FLT_MAX;
    for (int t = lane; t < H_ * H_; t += 32) {
        float v = f[t];
        int y = t / H_;
        int x = t - y * H_;
        bool in = (y >= y1) & (y <= y2) & (x >= x1) & (x <= x2);
        m = fmaxf(m, in ? v : -FLT_MAX);
    }
    #pragma unroll
    for (int o = 16; o; o >>= 1) m = fmaxf(m, __shfl_xor_sync(0xffffffffu, m, o));
    if (lane == 0) g_feat[b*C_ + c] = m;
}

// ---------------------------------------------------------------------------
// Kernel 3: fp16 2-term mma.sync GEMM with ldmatrix fragments.
//   part[split][128][HID_] = A[128, Ktot] @ Bw[Ktot, HID_]
//   BM=128, BN=64, BK=32; 8 warps, warp tile 32x32.
//   SMEM: A f16 [row][k] (80B pitch), Bhi/Blo f16 [k][n] (144B pitch).
//   Fragments via ldmatrix.x4 (A) / ldmatrix.x4.trans (B) — conflict-free.
// ---------------------------------------------------------------------------
#define APITCH_U32 20            // 80 B per A row (64B data + 16B pad)
#define BPITCH_U32 36            // 144 B per B k-row (128B data + 16B pad)
#define A_SZ   (128*APITCH_U32)  // 2560 u32 = 10240 B
#define B_SZ   (32*BPITCH_U32)   // 1152 u32 = 4608 B
#define BUFSZ  (A_SZ + 2*B_SZ)   // 4864 u32 = 19456 B

__global__ __launch_bounds__(256, 2)
void gemm_f16_kernel(int Ktot, int KSPLIT,
                     const float* __restrict__ A, const float* __restrict__ Bw,
                     float* __restrict__ part)
{
    extern __shared__ uint32_t sm[];

    const int tid  = threadIdx.x;
    const int wid  = tid >> 5;
    const int lane = tid & 31;
    const int gid  = lane >> 2;
    const int tig  = lane & 3;
    const int n0   = blockIdx.x * 64;
    const int ks   = blockIdx.y * KSPLIT;
    const int NCH  = KSPLIT >> 5;
    const int mbase = (wid & 3) * 32;
    const int nbase = (wid >> 2) * 32;

    // B staging: thread owns (p, nq): k rows 2p,2p+1, col quad nq*4..+3
    const int bp_p  = tid >> 4;      // 0..15
    const int bp_nq = tid & 15;      // 0..15

    const uint32_t sbase = (uint32_t)__cvta_generic_to_shared(sm);

    // per-lane ldmatrix byte offsets (within a buffer)
    const int l15  = lane & 15;
    const int lhi8 = (lane >> 4) * 8;
    // A: lanes 0-15 rows mbase+l15 (k=s*16), lanes 16-31 same rows k=s*16+8
    const uint32_t a_off = (uint32_t)((mbase + l15) * 80 + lhi8 * 2);
    // B: lanes 0-15 k-rows l15 (n=nbase+ntp*16), lanes 16-31 n +8
    const uint32_t b_off = (uint32_t)(l15 * 144 + (nbase + lhi8) * 2);

    float acc[2][4][4];
    #pragma unroll
    for (int i = 0; i < 2; i++)
        #pragma unroll
        for (int j = 0; j < 4; j++)
            #pragma unroll
            for (int q = 0; q < 4; q++) acc[i][j][q] = 0.f;

    float4 ra[4];
    float4 rb0, rb1;

    #define LOAD_REGS(k0) do {                                              \
        _Pragma("unroll")                                                   \
        for (int j = 0; j < 4; j++) {                                       \
            int f4 = tid + j * 256;                                         \
            int row = f4 >> 3, q = f4 & 7;                                  \
            ra[j] = *(const float4*)(A + (size_t)row * Ktot + (k0) + q * 4);\
        }                                                                   \
        {                                                                   \
            const float* bp = Bw + (size_t)((k0) + 2 * bp_p) * HID_         \
                              + n0 + bp_nq * 4;                             \
            rb0 = *(const float4*)bp;                                       \
            rb1 = *(const float4*)(bp + HID_);                              \
        }                                                                   \
    } while (0)

    // A plane: f16 [row][k], u32 index row*20 + k/2
    // B planes: f16 [k][n],  u32 index k*36 + n/2
    #define STORE_SMEM(buf) do {                                            \
        uint32_t* Ah = sm + (buf) * BUFSZ;                                  \
        uint32_t* Bh = Ah + A_SZ;                                           \
        uint32_t* Bl = Bh + B_SZ;                                           \
        _Pragma("unroll")                                                   \
        for (int j = 0; j < 4; j++) {                                       \
            int f4 = tid + j * 256;                                         \
            int row = f4 >> 3, q = f4 & 7;                                  \
            uint32_t h0 = pack2_f16(ra[j].x, ra[j].y);                      \
            uint32_t h1 = pack2_f16(ra[j].z, ra[j].w);                      \
            *(uint2*)&Ah[row * APITCH_U32 + q * 2] = make_uint2(h0, h1);    \
        }                                                                   \
        {                                                                   \
            uint32_t h00 = pack2_f16(rb0.x, rb0.y), h01 = pack2_f16(rb0.z, rb0.w); \
            uint32_t h10 = pack2_f16(rb1.x, rb1.y), h11 = pack2_f16(rb1.z, rb1.w); \
            __half lx0 = __float2half_rn(rb0.x - __half2float(__float2half_rn(rb0.x))); \
            __half lx1 = __float2half_rn(rb0.y - __half2float(__float2half_rn(rb0.y))); \
            __half lx2 = __float2half_rn(rb0.z - __half2float(__float2half_rn(rb0.z))); \
            __half lx3 = __float2half_rn(rb0.w - __half2float(__float2half_rn(rb0.w))); \
            __half ly0 = __float2half_rn(rb1.x - __half2float(__float2half_rn(rb1.x))); \
            __half ly1 = __float2half_rn(rb1.y - __half2float(__float2half_rn(rb1.y))); \
            __half ly2 = __float2half_rn(rb1.z - __half2float(__float2half_rn(rb1.z))); \
            __half ly3 = __float2half_rn(rb1.w - __half2float(__float2half_rn(rb1.w))); \
            uint32_t l00 = (uint32_t)__half_as_ushort(lx0) | ((uint32_t)__half_as_ushort(lx1) << 16); \
            uint32_t l01 = (uint32_t)__half_as_ushort(lx2) | ((uint32_t)__half_as_ushort(lx3) << 16); \
            uint32_t l10 = (uint32_t)__half_as_ushort(ly0) | ((uint32_t)__half_as_ushort(ly1) << 16); \
            uint32_t l11 = (uint32_t)__half_as_ushort(ly2) | ((uint32_t)__half_as_ushort(ly3) << 16); \
            int r0 = (2*bp_p)     * BPITCH_U32 + bp_nq * 2;                 \
            int r1 = (2*bp_p + 1) * BPITCH_U32 + bp_nq * 2;                 \
            *(uint2*)&Bh[r0] = make_uint2(h00, h01);                        \
            *(uint2*)&Bh[r1] = make_uint2(h10, h11);                        \
            *(uint2*)&Bl[r0] = make_uint2(l00, l01);                        \
            *(uint2*)&Bl[r1] = make_uint2(l10, l11);                        \
        }                                                                   \
    } while (0)

    LOAD_REGS(ks);
    STORE_SMEM(0);
    if (NCH > 1) LOAD_REGS(ks + 32);
    __syncthreads();

    for (int c = 0; c < NCH; c++) {
        const int buf = c & 1;
        const uint32_t AhA = sbase + (uint32_t)(buf * (BUFSZ * 4)) + a_off;
        const uint32_t BhA = sbase + (uint32_t)(buf * (BUFSZ * 4) + A_SZ * 4) + b_off;
        const uint32_t BlA = BhA + (uint32_t)(B_SZ * 4);

        #pragma unroll
        for (int s = 0; s < 2; s++) {
            // A fragments: mt=0,1 (16-row stride = 1280 B); s stride = 32 B
            uint32_t a[2][4];
            LDSM_X4(a[0], AhA + s * 32);
            LDSM_X4(a[1], AhA + s * 32 + 1280);
            // B fragments: ntp=0,1 (16-col stride = 32 B); s stride = 16*144 B
            uint32_t bh[2][4], bl[2][4];
            LDSM_X4T(bh[0], BhA + s * (16*144));
            LDSM_X4T(bh[1], BhA + s * (16*144) + 32);
            LDSM_X4T(bl[0], BlA + s * (16*144));
            LDSM_X4T(bl[1], BlA + s * (16*144) + 32);

            #pragma unroll
            for (int mt = 0; mt < 2; mt++) {
                #pragma unroll
                for (int ntp = 0; ntp < 2; ntp++) {
                    MMA_F16(acc[mt][2*ntp+0], a[mt], bh[ntp][0], bh[ntp][1]);
                    MMA_F16(acc[mt][2*ntp+0], a[mt], bl[ntp][0], bl[ntp][1]);
                    MMA_F16(acc[mt][2*ntp+1], a[mt], bh[ntp][2], bh[ntp][3]);
                    MMA_F16(acc[mt][2*ntp+1], a[mt], bl[ntp][2], bl[ntp][3]);
                }
            }
        }

        if (c + 1 < NCH) STORE_SMEM(buf ^ 1);
        if (c + 2 < NCH) LOAD_REGS(ks + (c + 2) * 32);
        __syncthreads();
    }

    // epilogue: partial sums
    #pragma unroll
    for (int mt = 0; mt < 2; mt++) {
        int row = mbase + mt * 16 + gid;
        float* base = part + ((size_t)blockIdx.y * 128 + row) * HID_ + n0 + nbase;
        #pragma unroll
        for (int nt = 0; nt < 4; nt++) {
            float* d = base + nt * 8 + tig * 2;
            *(float2*)d               = make_float2(acc[mt][nt][0], acc[mt][nt][1]);
            *(float2*)(d + 8 * HID_)  = make_float2(acc[mt][nt][2], acc[mt][nt][3]);
        }
    }
    #undef LOAD_REGS
    #undef STORE_SMEM
}

// ---------------------------------------------------------------------------
// Kernel 4: split-K reduce + bias + relu
// ---------------------------------------------------------------------------
template<bool RELU>
__global__ void reduce_bias_kernel(int S, const float* __restrict__ part,
                                   const float* __restrict__ bias,
                                   float* __restrict__ out)
{
    int i4 = blockIdx.x * 256 + threadIdx.x;
    const int MN = B_ * HID_;
    int base = i4 * 4;
    if (base >= MN) return;
    float4 s = make_float4(0.f, 0.f, 0.f, 0.f);
    for (int p = 0; p < S; p++) {
        float4 v = *(const float4*)(part + (size_t)p * MN + base);
        s.x += v.x; s.y += v.y; s.z += v.z; s.w += v.w;
    }
    int n = base & (HID_ - 1);
    s.x += bias[n + 0]; s.y += bias[n + 1]; s.z += bias[n + 2]; s.w += bias[n + 3];
    if (RELU) {
        s.x = fmaxf(s.x, 0.f); s.y = fmaxf(s.y, 0.f);
        s.z = fmaxf(s.z, 0.f); s.w = fmaxf(s.w, 0.f);
    }
    *(float4*)(out + base) = s;
}

// ---------------------------------------------------------------------------
// Kernel 5: final FC  out[B,19] = h2 @ w3 + b3
// ---------------------------------------------------------------------------
__global__ void fc3_kernel(const float* __restrict__ A, const float* __restrict__ W,
                           const float* __restrict__ bias, float* __restrict__ out)
{
    int b = blockIdx.x;
    int tid = threadIdx.x, warp = tid >> 5, lane = tid & 31;
    __shared__ float sh[HID_];
    const float* a = A + (size_t)b * HID_;
    for (int i = tid; i < HID_; i += 256) sh[i] = a[i];
    __syncthreads();
    for (int col = warp; col < FG_; col += 8) {
        float s = 0.f;
        for (int k = lane; k < HID_; k += 32) s += sh[k] * W[(size_t)k * FG_ + col];
        #pragma unroll
        for (int o = 16; o; o >>= 1) s += __shfl_xor_sync(0xffffffffu, s, o);
        if (lane == 0) out[b * FG_ + col] = s + bias[col];
    }
}

// ---------------------------------------------------------------------------
extern "C" void kernel_launch(void* const* d_in, const int* in_sizes, int n_in,
                              void* d_out, int out_size)
{
    const float* loc      = (const float*)d_in[0];
    const float* conf     = (const float*)d_in[1];
    const float* priors   = (const float*)d_in[2];
    const float* features = (const float*)d_in[3];
    const float* w1 = (const float*)d_in[4];
    const float* b1 = (const float*)d_in[5];
    const float* w2 = (const float*)d_in[6];
    const float* b2 = (const float*)d_in[7];
    const float* w3 = (const float*)d_in[8];
    const float* b3 = (const float*)d_in[9];
    float* out = (float*)d_out;

    void *pf, *p1, *p2, *ppart;
    cudaGetSymbolAddress(&pf,    g_feat);
    cudaGetSymbolAddress(&p1,    g_h1);
    cudaGetSymbolAddress(&p2,    g_h2);
    cudaGetSymbolAddress(&ppart, g_part);

    const int SMEM = 2 * BUFSZ * 4;   // 38912 B
    cudaFuncSetAttribute(gemm_f16_kernel,
                         cudaFuncAttributeMaxDynamicSharedMemorySize, SMEM);

    best_prior_kernel<<<B_, 256>>>(loc, conf, priors, out);
    extract_kernel<<<dim3(B_, C_/8), 256>>>(features);

    // GEMM1: [128,512] @ [512,4096], split-K=4 (KSPLIT=128, NCH=4)
    gemm_f16_kernel<<<dim3(HID_/64, 4), 256, SMEM>>>(C_, 128,
        (const float*)pf, w1, (float*)ppart);
    reduce_bias_kernel<true><<<(B_*HID_/4 + 255)/256, 256>>>(4,
        (const float*)ppart, b1, (float*)p1);

    // GEMM2: [128,4096] @ [4096,4096], split-K=4 (KSPLIT=1024, NCH=32)
    // 256 CTAs => single co-resident wave at 2 CTAs/SM
    gemm_f16_kernel<<<dim3(HID_/64, 4), 256, SMEM>>>(HID_, 1024,
        (const float*)p1, w2, (float*)ppart);
    reduce_bias_kernel<true><<<(B_*HID_/4 + 255)/256, 256>>>(4,
        (const float*)ppart, b2, (float*)p2);

    fc3_kernel<<<B_, 256>>>((const float*)p2, w3, b3, out);
}

// round 9
// speedup vs baseline: 3.0719x; 1.1492x over previous
#include <cuda_runtime.h>
#include <cuda_fp16.h>
#include <math.h>
#include <cfloat>
#include <cstdint>

#define B_   128
#define N_   8732
#define C_   512
#define H_   19
#define FG_  19
#define HID_ 4096

// ---------------------------------------------------------------------------
// scratch (device globals — no allocation allowed)
// ---------------------------------------------------------------------------
__device__ float g_feat[B_*C_];
__device__ float g_h1[B_*HID_];
__device__ float g_h2[B_*HID_];
__device__ int   g_bins[B_*4];
__device__ int   g_valid[B_];
__device__ float g_part[4*B_*HID_];     // split-K partials (S<=4)
__device__ float g_w3t[FG_*HID_];       // w3 transposed [19][4096]

// ---------------------------------------------------------------------------
// helpers
// ---------------------------------------------------------------------------
#define MMA_F16(c, a, b0, b1)                                               \
    asm volatile("mma.sync.aligned.m16n8k16.row.col.f32.f16.f16.f32 "       \
        "{%0,%1,%2,%3}, {%4,%5,%6,%7}, {%8,%9}, {%0,%1,%2,%3};"             \
        : "+f"((c)[0]), "+f"((c)[1]), "+f"((c)[2]), "+f"((c)[3])            \
        : "r"((a)[0]), "r"((a)[1]), "r"((a)[2]), "r"((a)[3]),               \
          "r"(b0), "r"(b1))

#define LDSM_X4(r, addr)                                                    \
    asm volatile("ldmatrix.sync.aligned.m8n8.x4.shared.b16 "                \
        "{%0,%1,%2,%3}, [%4];"                                              \
        : "=r"((r)[0]), "=r"((r)[1]), "=r"((r)[2]), "=r"((r)[3])            \
        : "r"(addr) : "memory")

#define LDSM_X4T(r, addr)                                                   \
    asm volatile("ldmatrix.sync.aligned.m8n8.x4.trans.shared.b16 "          \
        "{%0,%1,%2,%3}, [%4];"                                              \
        : "=r"((r)[0]), "=r"((r)[1]), "=r"((r)[2]), "=r"((r)[3])            \
        : "r"(addr) : "memory")

__device__ __forceinline__ uint32_t pack2_f16(float x0, float x1)
{
    __half2 h = __floats2half2_rn(x0, x1);
    return *(uint32_t*)&h;
}

// ---------------------------------------------------------------------------
// Kernel 1: per-batch best car prior -> decode -> clip -> boxes/valid + bins
// ---------------------------------------------------------------------------
__global__ void best_prior_kernel(const float* __restrict__ loc,
                                  const float* __restrict__ conf,
                                  const float* __restrict__ priors,
                                  float* __restrict__ out)
{
    int b = blockIdx.x, tid = threadIdx.x;
    const float2* cb = (const float2*)(conf + (size_t)b * N_ * 2);

    float best = -FLT_MAX;
    int   bidx = 0x7fffffff;
    int   anyc = 0;

    for (int i = tid; i < N_; i += 256) {
        float2 c = cb[i];
        if (c.y > c.x) {
            anyc = 1;
            float p1 = 1.0f / (1.0f + expf(c.x - c.y));
            if (p1 > best || (p1 == best && i < bidx)) { best = p1; bidx = i; }
        }
    }

    int has = __syncthreads_or(anyc);

    __shared__ float sv[256];
    __shared__ int   si[256];
    sv[tid] = best; si[tid] = bidx;
    __syncthreads();
    for (int s = 128; s > 0; s >>= 1) {
        if (tid < s) {
            float v2 = sv[tid+s]; int i2 = si[tid+s];
            if (v2 > sv[tid] || (v2 == sv[tid] && i2 < si[tid])) { sv[tid]=v2; si[tid]=i2; }
        }
        __syncthreads();
    }

    if (tid == 0) {
        float bx0=0.f,bx1=0.f,bx2=0.f,bx3=0.f;
        int v = 0;
        int n0=0,n1=0,n2=0,n3=0;
        if (has) {
            int idx = si[0];
            float p0 = priors[4*idx+0], p1p = priors[4*idx+1];
            float p2 = priors[4*idx+2], p3  = priors[4*idx+3];
            const float* l = loc + ((size_t)b * N_ + idx) * 4;
            float cx = p0 + l[0] * 0.1f * p2;
            float cy = p1p + l[1] * 0.1f * p3;
            float w  = p2 * expf(l[2] * 0.2f);
            float h  = p3 * expf(l[3] * 0.2f);
            float x1 = cx - 0.5f*w, y1 = cy - 0.5f*h;
            float x2 = x1 + w,      y2 = y1 + h;
            v = (x2 > x1) && (y2 > y1);
            bx0 = fminf(fmaxf(x1, 0.f), 1.f);
            bx1 = fminf(fmaxf(y1, 0.f), 1.f);
            bx2 = fminf(fmaxf(x2, 0.f), 1.f);
            bx3 = fminf(fmaxf(y2, 0.f), 1.f);
            const float step = (float)(300.0 / 19.0);
            float t;
            t = fminf(fmaxf(bx0*300.0f,0.f),300.f)/step; n0 = (int)floorf(fminf(fmaxf(t,0.f),18.f));
            t = fminf(fmaxf(bx1*300.0f,0.f),300.f)/step; n1 = (int)floorf(fminf(fmaxf(t,0.f),18.f));
            t = fminf(fmaxf(bx2*300.0f,0.f),300.f)/step; n2 = (int)floorf(fminf(fmaxf(t,0.f),18.f));
            t = fminf(fmaxf(bx3*300.0f,0.f),300.f)/step; n3 = (int)floorf(fminf(fmaxf(t,0.f),18.f));
        }
        out[2432 + b*4 + 0] = bx0;
        out[2432 + b*4 + 1] = bx1;
        out[2432 + b*4 + 2] = bx2;
        out[2432 + b*4 + 3] = bx3;
        out[2944 + b] = v ? 1.0f : 0.0f;
        g_valid[b]   = v;
        g_bins[b*4+0] = n0; g_bins[b*4+1] = n1;
        g_bins[b*4+2] = n2; g_bins[b*4+3] = n3;
    }
}

// ---------------------------------------------------------------------------
// Kernel 2: masked global max pool -> g_feat [B, C]  (coalesced channel scan)
// ---------------------------------------------------------------------------
__global__ void extract_kernel(const float* __restrict__ feats)
{
    int b    = blockIdx.x;
    int warp = threadIdx.x >> 5;
    int lane = threadIdx.x & 31;
    int c    = blockIdx.y * 8 + warp;

    if (!g_valid[b]) { if (lane == 0) g_feat[b*C_ + c] = 0.f; return; }

    int x1 = g_bins[b*4+0], y1 = g_bins[b*4+1];
    int x2 = g_bins[b*4+2], y2 = g_bins[b*4+3];

    const float* f = feats + ((size_t)(b * C_ + c)) * (H_ * H_);
    float m = -FLT_MAX;
    for (int t = lane; t < H_ * H_; t += 32) {
        float v = f[t];
        int y = t / H_;
        int x = t - y * H_;
        bool in = (y >= y1) & (y <= y2) & (x >= x1) & (x <= x2);
        m = fmaxf(m, in ? v : -FLT_MAX);
    }
    #pragma unroll
    for (int o = 16; o; o >>= 1) m = fmaxf(m, __shfl_xor_sync(0xffffffffu, m, o));
    if (lane == 0) g_feat[b*C_ + c] = m;
}

// ---------------------------------------------------------------------------
// Kernel 3: single-term fp16 mma.sync GEMM with ldmatrix fragments.
//   part[split][128][HID_] = f16(A)[128, Ktot] @ f16(Bw)[Ktot, HID_]  (f32 acc)
//   BM=128, BN=64, BK=32; 8 warps, warp tile 32x32.
//   SMEM: A f16 [row][k] (80B pitch), B f16 [k][n] (144B pitch).
// ---------------------------------------------------------------------------
#define APITCH_U32 20            // 80 B per A row (64B data + 16B pad)
#define BPITCH_U32 36            // 144 B per B k-row (128B data + 16B pad)
#define A_SZ   (128*APITCH_U32)  // 2560 u32 = 10240 B
#define B_SZ   (32*BPITCH_U32)   // 1152 u32 = 4608 B
#define BUFSZ  (A_SZ + B_SZ)     // 3712 u32 = 14848 B

__global__ __launch_bounds__(256, 2)
void gemm_f16_kernel(int Ktot, int KSPLIT,
                     const float* __restrict__ A, const float* __restrict__ Bw,
                     float* __restrict__ part)
{
    extern __shared__ uint32_t sm[];

    const int tid  = threadIdx.x;
    const int wid  = tid >> 5;
    const int lane = tid & 31;
    const int gid  = lane >> 2;
    const int tig  = lane & 3;
    const int n0   = blockIdx.x * 64;
    const int ks   = blockIdx.y * KSPLIT;
    const int NCH  = KSPLIT >> 5;
    const int mbase = (wid & 3) * 32;
    const int nbase = (wid >> 2) * 32;

    // B staging: thread owns (p, nq): k rows 2p,2p+1, col quad nq*4..+3
    const int bp_p  = tid >> 4;      // 0..15
    const int bp_nq = tid & 15;      // 0..15

    const uint32_t sbase = (uint32_t)__cvta_generic_to_shared(sm);

    const int l15  = lane & 15;
    const int lhi8 = (lane >> 4) * 8;
    const uint32_t a_off = (uint32_t)((mbase + l15) * 80 + lhi8 * 2);
    const uint32_t b_off = (uint32_t)(l15 * 144 + (nbase + lhi8) * 2);

    float acc[2][4][4];
    #pragma unroll
    for (int i = 0; i < 2; i++)
        #pragma unroll
        for (int j = 0; j < 4; j++)
            #pragma unroll
            for (int q = 0; q < 4; q++) acc[i][j][q] = 0.f;

    float4 ra[4];
    float4 rb0, rb1;

    #define LOAD_REGS(k0) do {                                              \
        _Pragma("unroll")                                                   \
        for (int j = 0; j < 4; j++) {                                       \
            int f4 = tid + j * 256;                                         \
            int row = f4 >> 3, q = f4 & 7;                                  \
            ra[j] = *(const float4*)(A + (size_t)row * Ktot + (k0) + q * 4);\
        }                                                                   \
        {                                                                   \
            const float* bp = Bw + (size_t)((k0) + 2 * bp_p) * HID_         \
                              + n0 + bp_nq * 4;                             \
            rb0 = *(const float4*)bp;                                       \
            rb1 = *(const float4*)(bp + HID_);                              \
        }                                                                   \
    } while (0)

    #define STORE_SMEM(buf) do {                                            \
        uint32_t* Ah = sm + (buf) * BUFSZ;                                  \
        uint32_t* Bh = Ah + A_SZ;                                           \
        _Pragma("unroll")                                                   \
        for (int j = 0; j < 4; j++) {                                       \
            int f4 = tid + j * 256;                                         \
            int row = f4 >> 3, q = f4 & 7;                                  \
            uint32_t h0 = pack2_f16(ra[j].x, ra[j].y);                      \
            uint32_t h1 = pack2_f16(ra[j].z, ra[j].w);                      \
            *(uint2*)&Ah[row * APITCH_U32 + q * 2] = make_uint2(h0, h1);    \
        }                                                                   \
        {                                                                   \
            uint32_t h00 = pack2_f16(rb0.x, rb0.y), h01 = pack2_f16(rb0.z, rb0.w); \
            uint32_t h10 = pack2_f16(rb1.x, rb1.y), h11 = pack2_f16(rb1.z, rb1.w); \
            int r0 = (2*bp_p)     * BPITCH_U32 + bp_nq * 2;                 \
            int r1 = (2*bp_p + 1) * BPITCH_U32 + bp_nq * 2;                 \
            *(uint2*)&Bh[r0] = make_uint2(h00, h01);                        \
            *(uint2*)&Bh[r1] = make_uint2(h10, h11);                        \
        }                                                                   \
    } while (0)

    LOAD_REGS(ks);
    STORE_SMEM(0);
    if (NCH > 1) LOAD_REGS(ks + 32);
    __syncthreads();

    for (int c = 0; c < NCH; c++) {
        const int buf = c & 1;
        const uint32_t AhA = sbase + (uint32_t)(buf * (BUFSZ * 4)) + a_off;
        const uint32_t BhA = sbase + (uint32_t)(buf * (BUFSZ * 4) + A_SZ * 4) + b_off;

        #pragma unroll
        for (int s = 0; s < 2; s++) {
            uint32_t a[2][4];
            LDSM_X4(a[0], AhA + s * 32);
            LDSM_X4(a[1], AhA + s * 32 + 1280);
            uint32_t bh[2][4];
            LDSM_X4T(bh[0], BhA + s * (16*144));
            LDSM_X4T(bh[1], BhA + s * (16*144) + 32);

            #pragma unroll
            for (int mt = 0; mt < 2; mt++) {
                #pragma unroll
                for (int ntp = 0; ntp < 2; ntp++) {
                    MMA_F16(acc[mt][2*ntp+0], a[mt], bh[ntp][0], bh[ntp][1]);
                    MMA_F16(acc[mt][2*ntp+1], a[mt], bh[ntp][2], bh[ntp][3]);
                }
            }
        }

        if (c + 1 < NCH) STORE_SMEM(buf ^ 1);
        if (c + 2 < NCH) LOAD_REGS(ks + (c + 2) * 32);
        __syncthreads();
    }

    // epilogue: partial sums
    #pragma unroll
    for (int mt = 0; mt < 2; mt++) {
        int row = mbase + mt * 16 + gid;
        float* base = part + ((size_t)blockIdx.y * 128 + row) * HID_ + n0 + nbase;
        #pragma unroll
        for (int nt = 0; nt < 4; nt++) {
            float* d = base + nt * 8 + tig * 2;
            *(float2*)d               = make_float2(acc[mt][nt][0], acc[mt][nt][1]);
            *(float2*)(d + 8 * HID_)  = make_float2(acc[mt][nt][2], acc[mt][nt][3]);
        }
    }
    #undef LOAD_REGS
    #undef STORE_SMEM
}

// ---------------------------------------------------------------------------
// Kernel 4: split-K reduce + bias + relu
// ---------------------------------------------------------------------------
template<bool RELU>
__global__ void reduce_bias_kernel(int S, const float* __restrict__ part,
                                   const float* __restrict__ bias,
                                   float* __restrict__ out)
{
    int i4 = blockIdx.x * 256 + threadIdx.x;
    const int MN = B_ * HID_;
    int base = i4 * 4;
    if (base >= MN) return;
    float4 s = make_float4(0.f, 0.f, 0.f, 0.f);
    for (int p = 0; p < S; p++) {
        float4 v = *(const float4*)(part + (size_t)p * MN + base);
        s.x += v.x; s.y += v.y; s.z += v.z; s.w += v.w;
    }
    int n = base & (HID_ - 1);
    s.x += bias[n + 0]; s.y += bias[n + 1]; s.z += bias[n + 2]; s.w += bias[n + 3];
    if (RELU) {
        s.x = fmaxf(s.x, 0.f); s.y = fmaxf(s.y, 0.f);
        s.z = fmaxf(s.z, 0.f); s.w = fmaxf(s.w, 0.f);
    }
    *(float4*)(out + base) = s;
}

// ---------------------------------------------------------------------------
// Kernel 5a: transpose w3 [4096,19] -> w3t [19,4096]
// ---------------------------------------------------------------------------
__global__ void w3t_kernel(const float* __restrict__ w3, float* __restrict__ w3t)
{
    int k = blockIdx.x * 256 + threadIdx.x;   // 4096 rows
    if (k >= HID_) return;
    #pragma unroll
    for (int c = 0; c < FG_; c++)
        w3t[c * HID_ + k] = w3[k * FG_ + c];
}

// ---------------------------------------------------------------------------
// Kernel 5b: final FC  out[b,col] = dot(h2[b], w3t[col]) + b3[col]
// one warp per (b, col); fully coalesced float4 loads
// ---------------------------------------------------------------------------
__global__ void fc3_kernel(const float* __restrict__ A, const float* __restrict__ Wt,
                           const float* __restrict__ bias, float* __restrict__ out)
{
    int gw   = blockIdx.x * 8 + (threadIdx.x >> 5);   // global warp id
    int lane = threadIdx.x & 31;
    if (gw >= B_ * FG_) return;
    int b = gw / FG_, col = gw - b * FG_;

    const float4* a = (const float4*)(A  + (size_t)b   * HID_);
    const float4* w = (const float4*)(Wt + (size_t)col * HID_);
    float s = 0.f;
    #pragma unroll 4
    for (int i = lane; i < HID_/4; i += 32) {
        float4 av = a[i], wv = w[i];
        s += av.x*wv.x + av.y*wv.y + av.z*wv.z + av.w*wv.w;
    }
    #pragma unroll
    for (int o = 16; o; o >>= 1) s += __shfl_xor_sync(0xffffffffu, s, o);
    if (lane == 0) out[b * FG_ + col] = s + bias[col];
}

// ---------------------------------------------------------------------------
extern "C" void kernel_launch(void* const* d_in, const int* in_sizes, int n_in,
                              void* d_out, int out_size)
{
    const float* loc      = (const float*)d_in[0];
    const float* conf     = (const float*)d_in[1];
    const float* priors   = (const float*)d_in[2];
    const float* features = (const float*)d_in[3];
    const float* w1 = (const float*)d_in[4];
    const float* b1 = (const float*)d_in[5];
    const float* w2 = (const float*)d_in[6];
    const float* b2 = (const float*)d_in[7];
    const float* w3 = (const float*)d_in[8];
    const float* b3 = (const float*)d_in[9];
    float* out = (float*)d_out;

    void *pf, *p1, *p2, *ppart, *pw3t;
    cudaGetSymbolAddress(&pf,    g_feat);
    cudaGetSymbolAddress(&p1,    g_h1);
    cudaGetSymbolAddress(&p2,    g_h2);
    cudaGetSymbolAddress(&ppart, g_part);
    cudaGetSymbolAddress(&pw3t,  g_w3t);

    const int SMEM = 2 * BUFSZ * 4;   // 29696 B
    cudaFuncSetAttribute(gemm_f16_kernel,
                         cudaFuncAttributeMaxDynamicSharedMemorySize, SMEM);

    best_prior_kernel<<<B_, 256>>>(loc, conf, priors, out);
    extract_kernel<<<dim3(B_, C_/8), 256>>>(features);
    w3t_kernel<<<HID_/256, 256>>>(w3, (float*)pw3t);

    // GEMM1: [128,512] @ [512,4096], split-K=4 (KSPLIT=128, NCH=4)
    gemm_f16_kernel<<<dim3(HID_/64, 4), 256, SMEM>>>(C_, 128,
        (const float*)pf, w1, (float*)ppart);
    reduce_bias_kernel<true><<<(B_*HID_/4 + 255)/256, 256>>>(4,
        (const float*)ppart, b1, (float*)p1);

    // GEMM2: [128,4096] @ [4096,4096], split-K=4 (KSPLIT=1024, NCH=32)
    gemm_f16_kernel<<<dim3(HID_/64, 4), 256, SMEM>>>(HID_, 1024,
        (const float*)p1, w2, (float*)ppart);
    reduce_bias_kernel<true><<<(B_*HID_/4 + 255)/256, 256>>>(4,
        (const float*)ppart, b2, (float*)p2);

    fc3_kernel<<<(B_*FG_ + 7)/8, 256>>>((const float*)p2, (const float*)pw3t, b3, out);
}